// round 2
// baseline (speedup 1.0000x reference)
#include <cuda_runtime.h>
#include <math.h>

// Problem constants
#define Bq 8
#define Tq 1024
#define Cq 1024
#define Hq 16
#define Dq 64
#define Mq (Bq * Tq)          // 8192 rows
#define BHq (Bq * Hq)         // 128

// ---------------------------------------------------------------------------
// Scratch (device globals; no dynamic allocation allowed)
// ---------------------------------------------------------------------------
__device__ float g_q[(size_t)BHq * Tq * Dq];     // [B,H,T,D]  32 MB
__device__ float g_k[(size_t)BHq * Tq * Dq];     // [B,H,T,D]  32 MB
__device__ float g_v[(size_t)BHq * Tq * Dq];     // [B,H,T,D]  32 MB
__device__ float g_ctx[(size_t)Mq * Cq];         // [B,T,C]    32 MB
__device__ float g_wq[(size_t)Cq * Cq];          // packed [C, H*D]
__device__ float g_wk[(size_t)Cq * Cq];
__device__ float g_wv[(size_t)Cq * Cq];
__device__ float g_wpT[(size_t)Cq * Cq];         // Wproj^T: [K=C, N=C]

// ---------------------------------------------------------------------------
// Weight repack: Wq/Wk/Wv [H,C,D] -> [C, H*D]
// ---------------------------------------------------------------------------
__global__ void repack_qkv_kernel(const float* __restrict__ W, float* __restrict__ P) {
    int i = blockIdx.x * blockDim.x + threadIdx.x;   // over C * (H*D) = 1M
    int c = i >> 10;
    int n = i & 1023;
    int h = n >> 6;
    int d = n & 63;
    P[i] = W[((size_t)h * Cq + c) * Dq + d];
}

// Wproj [N,K] row-major -> WprojT [K,N]
__global__ void repack_projT_kernel(const float* __restrict__ W, float* __restrict__ P) {
    int i = blockIdx.x * blockDim.x + threadIdx.x;   // over C*C
    int k = i >> 10;
    int n = i & 1023;
    P[i] = W[(size_t)n * Cq + k];
}

// ---------------------------------------------------------------------------
// SGEMM 128x128x16, 256 threads, 8x8 per thread.
// mode 0: Cout[m*N+n] = acc + bias[n]   (row-major, bias optional)
// mode 1: scatter to [B,H,T,D]: m=(b,t), n=(h,d)
// ---------------------------------------------------------------------------
__global__ __launch_bounds__(256) void sgemm128(
    const float* __restrict__ A, const float* __restrict__ Bm,
    float* __restrict__ Cout, int K, int N, int mode,
    const float* __restrict__ bias)
{
    __shared__ float As[16][132];   // padded
    __shared__ float Bs[16][128];

    const int tid  = threadIdx.x;
    const int row0 = blockIdx.y * 128;
    const int col0 = blockIdx.x * 128;
    const int tr   = (tid >> 4) << 3;   // 0..120
    const int tc   = (tid & 15) << 3;

    float acc[8][8];
#pragma unroll
    for (int i = 0; i < 8; i++)
#pragma unroll
        for (int j = 0; j < 8; j++) acc[i][j] = 0.f;

    for (int k0 = 0; k0 < K; k0 += 16) {
#pragma unroll
        for (int l = 0; l < 2; l++) {
            int f  = tid + l * 256;
            // A tile: 128 rows x 16 cols (4 float4 per row)
            int ra = f >> 2, ca = (f & 3) << 2;
            float4 va = *(const float4*)(A + (size_t)(row0 + ra) * K + k0 + ca);
            As[ca + 0][ra] = va.x;
            As[ca + 1][ra] = va.y;
            As[ca + 2][ra] = va.z;
            As[ca + 3][ra] = va.w;
            // B tile: 16 rows x 128 cols
            int rb = f >> 5, cb = (f & 31) << 2;
            float4 vb = *(const float4*)(Bm + (size_t)(k0 + rb) * N + col0 + cb);
            *(float4*)(&Bs[rb][cb]) = vb;
        }
        __syncthreads();

#pragma unroll
        for (int kk = 0; kk < 16; kk++) {
            float rm[8], rn[8];
#pragma unroll
            for (int i = 0; i < 8; i++) rm[i] = As[kk][tr + i];
#pragma unroll
            for (int j = 0; j < 8; j++) rn[j] = Bs[kk][tc + j];
#pragma unroll
            for (int i = 0; i < 8; i++)
#pragma unroll
                for (int j = 0; j < 8; j++)
                    acc[i][j] = fmaf(rm[i], rn[j], acc[i][j]);
        }
        __syncthreads();
    }

    if (mode == 0) {
#pragma unroll
        for (int i = 0; i < 8; i++) {
            int m = row0 + tr + i;
#pragma unroll
            for (int j = 0; j < 8; j++) {
                int n = col0 + tc + j;
                float v = acc[i][j];
                if (bias) v += bias[n];
                Cout[(size_t)m * N + n] = v;
            }
        }
    } else {
#pragma unroll
        for (int i = 0; i < 8; i++) {
            int m = row0 + tr + i;
            int b = m >> 10, t = m & 1023;
#pragma unroll
            for (int j = 0; j < 8; j++) {
                int n = col0 + tc + j;
                int h = n >> 6, d = n & 63;
                Cout[((size_t)(b * Hq + h) * Tq + t) * Dq + d] = acc[i][j];
            }
        }
    }
}

// ---------------------------------------------------------------------------
// Scores: S[t,s] = q[t]·k[s] / 8 for lower-triangular 64x64 tiles.
// grid (sTile=16, tTile=16, bh=128). Blocks with sTile>tTile skipped.
// ---------------------------------------------------------------------------
__global__ __launch_bounds__(256) void scores_kernel(float* __restrict__ wei) {
    int sT = blockIdx.x, tT = blockIdx.y, bh = blockIdx.z;
    if (sT > tT) return;

    __shared__ float Qs[64][65];   // [d][t]
    __shared__ float Ks[64][65];   // [d][s]
    int tid = threadIdx.x;

    const float* qb = g_q + (size_t)bh * Tq * Dq + (size_t)tT * 64 * Dq;
    const float* kb = g_k + (size_t)bh * Tq * Dq + (size_t)sT * 64 * Dq;

#pragma unroll
    for (int l = 0; l < 4; l++) {
        int f = tid + l * 256;
        int r = f >> 4, c4 = (f & 15) << 2;
        float4 vq = *(const float4*)(qb + r * Dq + c4);
        Qs[c4 + 0][r] = vq.x; Qs[c4 + 1][r] = vq.y;
        Qs[c4 + 2][r] = vq.z; Qs[c4 + 3][r] = vq.w;
        float4 vk = *(const float4*)(kb + r * Dq + c4);
        Ks[c4 + 0][r] = vk.x; Ks[c4 + 1][r] = vk.y;
        Ks[c4 + 2][r] = vk.z; Ks[c4 + 3][r] = vk.w;
    }
    __syncthreads();

    int tr = (tid >> 4) << 2;   // t within tile
    int tc = (tid & 15) << 2;   // s within tile
    float acc[4][4];
#pragma unroll
    for (int i = 0; i < 4; i++)
#pragma unroll
        for (int j = 0; j < 4; j++) acc[i][j] = 0.f;

#pragma unroll
    for (int kk = 0; kk < 64; kk++) {
        float rq[4], rk[4];
#pragma unroll
        for (int i = 0; i < 4; i++) rq[i] = Qs[kk][tr + i];
#pragma unroll
        for (int j = 0; j < 4; j++) rk[j] = Ks[kk][tc + j];
#pragma unroll
        for (int i = 0; i < 4; i++)
#pragma unroll
            for (int j = 0; j < 4; j++)
                acc[i][j] = fmaf(rq[i], rk[j], acc[i][j]);
    }

    float* w = wei + (size_t)bh * Tq * Tq + (size_t)(tT * 64) * Tq + sT * 64;
#pragma unroll
    for (int i = 0; i < 4; i++)
#pragma unroll
        for (int j = 0; j < 4; j++)
            w[(size_t)(tr + i) * Tq + tc + j] = acc[i][j] * 0.125f;
}

// ---------------------------------------------------------------------------
// Row softmax with causal mask, in place. One block per row (B*H*T rows).
// Writes exact 0 for s > t.
// ---------------------------------------------------------------------------
__global__ __launch_bounds__(256) void softmax_kernel(float* __restrict__ wei) {
    int row = blockIdx.x;
    int t   = row & (Tq - 1);
    float* p = wei + (size_t)row * Tq;
    int tid  = threadIdx.x;

    float vals[4];
    float mx = -INFINITY;
#pragma unroll
    for (int u = 0; u < 4; u++) {
        int s = tid + u * 256;
        vals[u] = (s <= t) ? p[s] : -INFINITY;
        mx = fmaxf(mx, vals[u]);
    }
#pragma unroll
    for (int o = 16; o; o >>= 1) mx = fmaxf(mx, __shfl_xor_sync(0xffffffffu, mx, o));

    __shared__ float red[8];
    if ((tid & 31) == 0) red[tid >> 5] = mx;
    __syncthreads();
    if (tid < 32) {
        float m2 = (tid < 8) ? red[tid] : -INFINITY;
#pragma unroll
        for (int o = 4; o; o >>= 1) m2 = fmaxf(m2, __shfl_xor_sync(0xffffffffu, m2, o));
        if (tid == 0) red[0] = m2;
    }
    __syncthreads();
    mx = red[0];
    __syncthreads();

    float sum = 0.f;
#pragma unroll
    for (int u = 0; u < 4; u++) {
        vals[u] = expf(vals[u] - mx);   // exp(-inf)=0 for masked lanes
        sum += vals[u];
    }
#pragma unroll
    for (int o = 16; o; o >>= 1) sum += __shfl_xor_sync(0xffffffffu, sum, o);
    if ((tid & 31) == 0) red[tid >> 5] = sum;
    __syncthreads();
    if (tid < 32) {
        float s2 = (tid < 8) ? red[tid] : 0.f;
#pragma unroll
        for (int o = 4; o; o >>= 1) s2 += __shfl_xor_sync(0xffffffffu, s2, o);
        if (tid == 0) red[0] = s2;
    }
    __syncthreads();
    float inv = 1.0f / red[0];

#pragma unroll
    for (int u = 0; u < 4; u++) {
        int s = tid + u * 256;
        p[s] = vals[u] * inv;
    }
}

// ---------------------------------------------------------------------------
// ctx = P @ V per (b,h). Block = 64 t-rows x 64 d-cols; loops over s-tiles
// up to the diagonal. Output written in [B,T,C] layout for the out-proj GEMM.
// ---------------------------------------------------------------------------
__global__ __launch_bounds__(256) void ctx_kernel(const float* __restrict__ wei) {
    int tT = blockIdx.x, bh = blockIdx.y;
    int b = bh >> 4, h = bh & 15;

    __shared__ float Ps[64][65];   // [s][t]
    __shared__ float Vs[64][64];   // [s][d]
    int tid = threadIdx.x;
    int tr = (tid >> 4) << 2;      // t within tile
    int tc = (tid & 15) << 2;      // d within tile

    float acc[4][4];
#pragma unroll
    for (int i = 0; i < 4; i++)
#pragma unroll
        for (int j = 0; j < 4; j++) acc[i][j] = 0.f;

    const float* wb = wei + (size_t)bh * Tq * Tq + (size_t)(tT * 64) * Tq;
    const float* vb = g_v + (size_t)bh * Tq * Dq;

    for (int sT = 0; sT <= tT; sT++) {
#pragma unroll
        for (int l = 0; l < 4; l++) {
            int f = tid + l * 256;
            int r = f >> 4, c4 = (f & 15) << 2;
            float4 vp = *(const float4*)(wb + (size_t)r * Tq + sT * 64 + c4);
            Ps[c4 + 0][r] = vp.x; Ps[c4 + 1][r] = vp.y;
            Ps[c4 + 2][r] = vp.z; Ps[c4 + 3][r] = vp.w;
            float4 vv = *(const float4*)(vb + (size_t)(sT * 64 + r) * Dq + c4);
            *(float4*)(&Vs[r][c4]) = vv;
        }
        __syncthreads();

#pragma unroll
        for (int kk = 0; kk < 64; kk++) {
            float rp[4], rv[4];
#pragma unroll
            for (int i = 0; i < 4; i++) rp[i] = Ps[kk][tr + i];
#pragma unroll
            for (int j = 0; j < 4; j++) rv[j] = Vs[kk][tc + j];
#pragma unroll
            for (int i = 0; i < 4; i++)
#pragma unroll
                for (int j = 0; j < 4; j++)
                    acc[i][j] = fmaf(rp[i], rv[j], acc[i][j]);
        }
        __syncthreads();
    }

#pragma unroll
    for (int i = 0; i < 4; i++) {
        int t = tT * 64 + tr + i;
#pragma unroll
        for (int j = 0; j < 4; j++) {
            g_ctx[(size_t)(b * Tq + t) * Cq + h * 64 + tc + j] = acc[i][j];
        }
    }
}

// ---------------------------------------------------------------------------
// Launch
// ---------------------------------------------------------------------------
extern "C" void kernel_launch(void* const* d_in, const int* in_sizes, int n_in,
                              void* d_out, int out_size) {
    const float* x     = (const float*)d_in[0];
    const float* Wq    = (const float*)d_in[1];
    const float* Wk    = (const float*)d_in[2];
    const float* Wv    = (const float*)d_in[3];
    const float* Wproj = (const float*)d_in[4];
    const float* bproj = (const float*)d_in[5];

    float* out = (float*)d_out;                       // [B,T,C]
    float* wei = out + (size_t)Bq * Tq * Cq;          // [B,H,T,T]

    float *pq, *pk, *pv, *pctx, *pwq, *pwk, *pwv, *pwpT;
    cudaGetSymbolAddress((void**)&pq,   g_q);
    cudaGetSymbolAddress((void**)&pk,   g_k);
    cudaGetSymbolAddress((void**)&pv,   g_v);
    cudaGetSymbolAddress((void**)&pctx, g_ctx);
    cudaGetSymbolAddress((void**)&pwq,  g_wq);
    cudaGetSymbolAddress((void**)&pwk,  g_wk);
    cudaGetSymbolAddress((void**)&pwv,  g_wv);
    cudaGetSymbolAddress((void**)&pwpT, g_wpT);

    // 1) repack weights
    repack_qkv_kernel<<<4096, 256>>>(Wq, pwq);
    repack_qkv_kernel<<<4096, 256>>>(Wk, pwk);
    repack_qkv_kernel<<<4096, 256>>>(Wv, pwv);
    repack_projT_kernel<<<4096, 256>>>(Wproj, pwpT);

    // 2) Q/K/V projections (scatter into [B,H,T,D])
    dim3 gproj(Cq / 128, Mq / 128);
    sgemm128<<<gproj, 256>>>(x, pwq, pq, Cq, Cq, 1, nullptr);
    sgemm128<<<gproj, 256>>>(x, pwk, pk, Cq, Cq, 1, nullptr);
    sgemm128<<<gproj, 256>>>(x, pwv, pv, Cq, Cq, 1, nullptr);

    // 3) scores (causal half only)
    dim3 gsc(Tq / 64, Tq / 64, BHq);
    scores_kernel<<<gsc, 256>>>(wei);

    // 4) softmax in place (writes zeros above diagonal)
    softmax_kernel<<<BHq * Tq, 256>>>(wei);

    // 5) ctx = P @ V  -> [B,T,C]
    dim3 gctx(Tq / 64, BHq);
    ctx_kernel<<<gctx, 256>>>(wei);

    // 6) out = ctx @ Wproj^T + b
    dim3 gout(Cq / 128, Mq / 128);
    sgemm128<<<gout, 256>>>(pctx, pwpT, out, Cq, Cq, 0, bproj);
}

// round 4
// speedup vs baseline: 1.4000x; 1.4000x over previous
#include <cuda_runtime.h>
#include <math.h>
#include <stdint.h>

// Problem constants
#define Bq 8
#define Tq 1024
#define Cq 1024
#define Hq 16
#define Dq 64
#define Mq (Bq * Tq)          // 8192 rows
#define BHq (Bq * Hq)         // 128

// ---------------------------------------------------------------------------
// Scratch (device globals; no dynamic allocation allowed)
// ---------------------------------------------------------------------------
__device__ float g_q[(size_t)BHq * Tq * Dq];      // [B,H,T,D]  32 MB
__device__ float g_k[(size_t)BHq * Tq * Dq];      // 32 MB
__device__ float g_v[(size_t)BHq * Tq * Dq];      // 32 MB
__device__ float g_ctx[(size_t)Mq * Cq];          // [B,T,C]    32 MB
__device__ float g_xt[(size_t)Mq * Cq];           // x, tf32-rounded   32 MB
__device__ float g_wqt[(size_t)Cq * Cq];          // [N=HD, K=C] tf32
__device__ float g_wkt[(size_t)Cq * Cq];
__device__ float g_wvt[(size_t)Cq * Cq];
__device__ float g_ctx3[(size_t)Mq * 3 * Cq];     // split ctx [M, 3C]  96 MB
__device__ float g_wp3[(size_t)Cq * 3 * Cq];      // split Wproj [N, 3C] 12 MB

__device__ __forceinline__ float f2tf32(float a) {
    uint32_t r;
    asm("cvt.rna.tf32.f32 %0, %1;" : "=r"(r) : "f"(a));
    return __uint_as_float(r);
}

// ---------------------------------------------------------------------------
// Conversion / repack kernels
// ---------------------------------------------------------------------------
__global__ void conv_x4_kernel(const float4* __restrict__ x, float4* __restrict__ xt) {
    int i = blockIdx.x * blockDim.x + threadIdx.x;    // over Mq*Cq/4 = 2M
    float4 v = x[i];
    v.x = f2tf32(v.x); v.y = f2tf32(v.y); v.z = f2tf32(v.z); v.w = f2tf32(v.w);
    xt[i] = v;
}

// Wq/Wk/Wv [H,C,D] -> [N=HD, K=C], tf32-rounded
__global__ void conv_wqkv_kernel(const float* __restrict__ W, float* __restrict__ P) {
    int i = blockIdx.x * blockDim.x + threadIdx.x;    // over 1M
    int n = i >> 10;           // h*64+d
    int c = i & 1023;
    int h = n >> 6, d = n & 63;
    P[(size_t)n * Cq + c] = f2tf32(W[((size_t)h * Cq + c) * Dq + d]);
}

// Wproj [N,K] -> [N, 3K] layout (hi | lo | hi)
__global__ void conv_wp3_kernel(const float* __restrict__ W, float* __restrict__ P) {
    int i = blockIdx.x * blockDim.x + threadIdx.x;    // over 1M
    int n = i >> 10;
    int c = i & 1023;
    float a  = W[(size_t)n * Cq + c];
    float hi = f2tf32(a);
    float lo = f2tf32(a - hi);
    size_t base = (size_t)n * (3 * Cq);
    P[base + c]           = hi;
    P[base + Cq + c]      = lo;
    P[base + 2 * Cq + c]  = hi;
}

// ctx [M,C] -> [M, 3C] layout (hi | hi | lo)
__global__ void conv_ctx3_kernel(const float* __restrict__ S, float* __restrict__ P) {
    int i = blockIdx.x * blockDim.x + threadIdx.x;    // over 8M
    int m = i >> 10;
    int c = i & 1023;
    float a  = S[(size_t)m * Cq + c];
    float hi = f2tf32(a);
    float lo = f2tf32(a - hi);
    size_t base = (size_t)m * (3 * Cq);
    P[base + c]           = hi;
    P[base + Cq + c]      = hi;
    P[base + 2 * Cq + c]  = lo;
}

// ---------------------------------------------------------------------------
// Warp-MMA tf32 GEMM. CTA tile 128x128, K-chunk 16, 256 threads (8 warps 4x2).
// A [Mtot,K] row-major; B [Ntot,K] row-major (K-major: computes A·B^T).
// mode 0: Cout[m*Nout+n] = acc (+bias[n]);  mode 1: scatter to [B,H,T,D].
// ---------------------------------------------------------------------------
#define SPAD 20   // row stride (floats): 20k mod 32 distinct for 8 rows -> conflict-free frags

__device__ __forceinline__ void mma_tf32(float c[4], uint32_t a0, uint32_t a1,
                                         uint32_t a2, uint32_t a3,
                                         uint32_t b0, uint32_t b1) {
    asm volatile(
        "mma.sync.aligned.m16n8k8.row.col.f32.tf32.tf32.f32 "
        "{%0,%1,%2,%3}, {%4,%5,%6,%7}, {%8,%9}, {%0,%1,%2,%3};"
        : "+f"(c[0]), "+f"(c[1]), "+f"(c[2]), "+f"(c[3])
        : "r"(a0), "r"(a1), "r"(a2), "r"(a3), "r"(b0), "r"(b1));
}

__global__ __launch_bounds__(256) void gemm_mma(
    const float* __restrict__ A, const float* __restrict__ Bw,
    float* __restrict__ Cout, int K, int Nout, int mode,
    const float* __restrict__ bias)
{
    __shared__ float As[128][SPAD];
    __shared__ float Bs[128][SPAD];

    const int tid  = threadIdx.x;
    const int wid  = tid >> 5;
    const int lane = tid & 31;
    const int row0 = blockIdx.y * 128;
    const int col0 = blockIdx.x * 128;
    const int wm   = (wid & 3) * 32;     // warp M offset within tile
    const int wn   = (wid >> 2) * 64;    // warp N offset within tile

    float acc[2][8][4];
#pragma unroll
    for (int mt = 0; mt < 2; mt++)
#pragma unroll
        for (int nt = 0; nt < 8; nt++)
#pragma unroll
            for (int j = 0; j < 4; j++) acc[mt][nt][j] = 0.f;

    // load geometry: f = tid + l*256, l=0..1; row = f>>2, c4 = (f&3)*4
    const int r0l = tid >> 2;                 // l=0 row (0..63)
    const int c4  = (tid & 3) << 2;

    const int NC = K >> 4;

    // prologue loads (chunk 0)
    float4 ra[2], rb[2];
#pragma unroll
    for (int l = 0; l < 2; l++) {
        int r = r0l + l * 64;
        ra[l] = *(const float4*)(A  + (size_t)(row0 + r) * K + c4);
        rb[l] = *(const float4*)(Bw + (size_t)(col0 + r) * K + c4);
    }

    for (int i = 0; i < NC; i++) {
        // store current chunk
#pragma unroll
        for (int l = 0; l < 2; l++) {
            int r = r0l + l * 64;
            As[r][c4 + 0] = ra[l].x; As[r][c4 + 1] = ra[l].y;
            As[r][c4 + 2] = ra[l].z; As[r][c4 + 3] = ra[l].w;
            Bs[r][c4 + 0] = rb[l].x; Bs[r][c4 + 1] = rb[l].y;
            Bs[r][c4 + 2] = rb[l].z; Bs[r][c4 + 3] = rb[l].w;
        }
        __syncthreads();

        // prefetch next chunk
        if (i + 1 < NC) {
            const int k0 = (i + 1) << 4;
#pragma unroll
            for (int l = 0; l < 2; l++) {
                int r = r0l + l * 64;
                ra[l] = *(const float4*)(A  + (size_t)(row0 + r) * K + k0 + c4);
                rb[l] = *(const float4*)(Bw + (size_t)(col0 + r) * K + k0 + c4);
            }
        }

        // compute on smem chunk: 2 k-steps of 8
#pragma unroll
        for (int ks = 0; ks < 2; ks++) {
            const int kb = ks * 8;
            const int arow = wm + (lane >> 2);
            const int acol = kb + (lane & 3);
            uint32_t af[2][4];
#pragma unroll
            for (int mt = 0; mt < 2; mt++) {
                af[mt][0] = __float_as_uint(As[arow + mt * 16    ][acol    ]);
                af[mt][1] = __float_as_uint(As[arow + mt * 16 + 8][acol    ]);
                af[mt][2] = __float_as_uint(As[arow + mt * 16    ][acol + 4]);
                af[mt][3] = __float_as_uint(As[arow + mt * 16 + 8][acol + 4]);
            }
            const int brow = wn + (lane >> 2);
            const int bcol = kb + (lane & 3);
            uint32_t bf[8][2];
#pragma unroll
            for (int nt = 0; nt < 8; nt++) {
                bf[nt][0] = __float_as_uint(Bs[brow + nt * 8][bcol    ]);
                bf[nt][1] = __float_as_uint(Bs[brow + nt * 8][bcol + 4]);
            }
#pragma unroll
            for (int mt = 0; mt < 2; mt++)
#pragma unroll
                for (int nt = 0; nt < 8; nt++)
                    mma_tf32(acc[mt][nt], af[mt][0], af[mt][1], af[mt][2], af[mt][3],
                             bf[nt][0], bf[nt][1]);
        }
        __syncthreads();
    }

    // epilogue: c0:(r, 2q) c1:(r, 2q+1) c2:(r+8, 2q) c3:(r+8, 2q+1)
    const int er = lane >> 2;
    const int ec = (lane & 3) << 1;
#pragma unroll
    for (int mt = 0; mt < 2; mt++) {
#pragma unroll
        for (int nt = 0; nt < 8; nt++) {
#pragma unroll
            for (int half = 0; half < 2; half++) {
                int m = row0 + wm + mt * 16 + er + half * 8;
#pragma unroll
                for (int j = 0; j < 2; j++) {
                    int n = col0 + wn + nt * 8 + ec + j;
                    float v = acc[mt][nt][half * 2 + j];
                    if (mode == 0) {
                        if (bias) v += bias[n];
                        Cout[(size_t)m * Nout + n] = v;
                    } else {
                        int b = m >> 10, t = m & 1023;
                        int h = n >> 6, d = n & 63;
                        Cout[((size_t)(b * Hq + h) << 16) + ((size_t)t << 6) + d] = v;
                    }
                }
            }
        }
    }
}

// ---------------------------------------------------------------------------
// Scores: S[t,s] = q[t]·k[s] / 8 for lower-triangular 64x64 tiles.
// ---------------------------------------------------------------------------
__global__ __launch_bounds__(256) void scores_kernel(float* __restrict__ wei) {
    int sT = blockIdx.x, tT = blockIdx.y, bh = blockIdx.z;
    if (sT > tT) return;

    __shared__ float Qs[64][65];
    __shared__ float Ks[64][65];
    int tid = threadIdx.x;

    const float* qb = g_q + (size_t)bh * Tq * Dq + (size_t)tT * 64 * Dq;
    const float* kb = g_k + (size_t)bh * Tq * Dq + (size_t)sT * 64 * Dq;

#pragma unroll
    for (int l = 0; l < 4; l++) {
        int f = tid + l * 256;
        int r = f >> 4, c4 = (f & 15) << 2;
        float4 vq = *(const float4*)(qb + r * Dq + c4);
        Qs[c4 + 0][r] = vq.x; Qs[c4 + 1][r] = vq.y;
        Qs[c4 + 2][r] = vq.z; Qs[c4 + 3][r] = vq.w;
        float4 vk = *(const float4*)(kb + r * Dq + c4);
        Ks[c4 + 0][r] = vk.x; Ks[c4 + 1][r] = vk.y;
        Ks[c4 + 2][r] = vk.z; Ks[c4 + 3][r] = vk.w;
    }
    __syncthreads();

    int tr = (tid >> 4) << 2;
    int tc = (tid & 15) << 2;
    float acc[4][4];
#pragma unroll
    for (int i = 0; i < 4; i++)
#pragma unroll
        for (int j = 0; j < 4; j++) acc[i][j] = 0.f;

#pragma unroll
    for (int kk = 0; kk < 64; kk++) {
        float rq[4], rk[4];
#pragma unroll
        for (int i = 0; i < 4; i++) rq[i] = Qs[kk][tr + i];
#pragma unroll
        for (int j = 0; j < 4; j++) rk[j] = Ks[kk][tc + j];
#pragma unroll
        for (int i = 0; i < 4; i++)
#pragma unroll
            for (int j = 0; j < 4; j++)
                acc[i][j] = fmaf(rq[i], rk[j], acc[i][j]);
    }

    float* w = wei + (size_t)bh * Tq * Tq + (size_t)(tT * 64) * Tq + sT * 64;
#pragma unroll
    for (int i = 0; i < 4; i++)
#pragma unroll
        for (int j = 0; j < 4; j++)
            w[(size_t)(tr + i) * Tq + tc + j] = acc[i][j] * 0.125f;
}

// ---------------------------------------------------------------------------
// Row softmax with causal mask, in place.
// ---------------------------------------------------------------------------
__global__ __launch_bounds__(256) void softmax_kernel(float* __restrict__ wei) {
    int row = blockIdx.x;
    int t   = row & (Tq - 1);
    float* p = wei + (size_t)row * Tq;
    int tid  = threadIdx.x;

    float vals[4];
    float mx = -INFINITY;
#pragma unroll
    for (int u = 0; u < 4; u++) {
        int s = tid + u * 256;
        vals[u] = (s <= t) ? p[s] : -INFINITY;
        mx = fmaxf(mx, vals[u]);
    }
#pragma unroll
    for (int o = 16; o; o >>= 1) mx = fmaxf(mx, __shfl_xor_sync(0xffffffffu, mx, o));

    __shared__ float red[8];
    if ((tid & 31) == 0) red[tid >> 5] = mx;
    __syncthreads();
    if (tid < 32) {
        float m2 = (tid < 8) ? red[tid] : -INFINITY;
#pragma unroll
        for (int o = 4; o; o >>= 1) m2 = fmaxf(m2, __shfl_xor_sync(0xffffffffu, m2, o));
        if (tid == 0) red[0] = m2;
    }
    __syncthreads();
    mx = red[0];
    __syncthreads();

    float sum = 0.f;
#pragma unroll
    for (int u = 0; u < 4; u++) {
        vals[u] = expf(vals[u] - mx);
        sum += vals[u];
    }
#pragma unroll
    for (int o = 16; o; o >>= 1) sum += __shfl_xor_sync(0xffffffffu, sum, o);
    if ((tid & 31) == 0) red[tid >> 5] = sum;
    __syncthreads();
    if (tid < 32) {
        float s2 = (tid < 8) ? red[tid] : 0.f;
#pragma unroll
        for (int o = 4; o; o >>= 1) s2 += __shfl_xor_sync(0xffffffffu, s2, o);
        if (tid == 0) red[0] = s2;
    }
    __syncthreads();
    float inv = 1.0f / red[0];

#pragma unroll
    for (int u = 0; u < 4; u++) {
        int s = tid + u * 256;
        p[s] = vals[u] * inv;
    }
}

// ---------------------------------------------------------------------------
// ctx = P @ V per (b,h). Output in [B,T,C] layout.
// ---------------------------------------------------------------------------
__global__ __launch_bounds__(256) void ctx_kernel(const float* __restrict__ wei) {
    int tT = blockIdx.x, bh = blockIdx.y;
    int b = bh >> 4, h = bh & 15;

    __shared__ float Ps[64][65];
    __shared__ float Vs[64][64];
    int tid = threadIdx.x;
    int tr = (tid >> 4) << 2;
    int tc = (tid & 15) << 2;

    float acc[4][4];
#pragma unroll
    for (int i = 0; i < 4; i++)
#pragma unroll
        for (int j = 0; j < 4; j++) acc[i][j] = 0.f;

    const float* wb = wei + (size_t)bh * Tq * Tq + (size_t)(tT * 64) * Tq;
    const float* vb = g_v + (size_t)bh * Tq * Dq;

    for (int sT = 0; sT <= tT; sT++) {
#pragma unroll
        for (int l = 0; l < 4; l++) {
            int f = tid + l * 256;
            int r = f >> 4, c4 = (f & 15) << 2;
            float4 vp = *(const float4*)(wb + (size_t)r * Tq + sT * 64 + c4);
            Ps[c4 + 0][r] = vp.x; Ps[c4 + 1][r] = vp.y;
            Ps[c4 + 2][r] = vp.z; Ps[c4 + 3][r] = vp.w;
            float4 vv = *(const float4*)(vb + (size_t)(sT * 64 + r) * Dq + c4);
            *(float4*)(&Vs[r][c4]) = vv;
        }
        __syncthreads();

#pragma unroll
        for (int kk = 0; kk < 64; kk++) {
            float rp[4], rv[4];
#pragma unroll
            for (int i = 0; i < 4; i++) rp[i] = Ps[kk][tr + i];
#pragma unroll
            for (int j = 0; j < 4; j++) rv[j] = Vs[kk][tc + j];
#pragma unroll
            for (int i = 0; i < 4; i++)
#pragma unroll
                for (int j = 0; j < 4; j++)
                    acc[i][j] = fmaf(rp[i], rv[j], acc[i][j]);
        }
        __syncthreads();
    }

#pragma unroll
    for (int i = 0; i < 4; i++) {
        int t = tT * 64 + tr + i;
#pragma unroll
        for (int j = 0; j < 4; j++) {
            g_ctx[(size_t)(b * Tq + t) * Cq + h * 64 + tc + j] = acc[i][j];
        }
    }
}

// ---------------------------------------------------------------------------
// Launch
// ---------------------------------------------------------------------------
extern "C" void kernel_launch(void* const* d_in, const int* in_sizes, int n_in,
                              void* d_out, int out_size) {
    const float* x     = (const float*)d_in[0];
    const float* Wq    = (const float*)d_in[1];
    const float* Wk    = (const float*)d_in[2];
    const float* Wv    = (const float*)d_in[3];
    const float* Wproj = (const float*)d_in[4];
    const float* bproj = (const float*)d_in[5];

    float* out = (float*)d_out;                       // [B,T,C]
    float* wei = out + (size_t)Bq * Tq * Cq;          // [B,H,T,T]

    float *pq, *pk, *pv, *pctx, *pxt, *pwq, *pwk, *pwv, *pctx3, *pwp3;
    cudaGetSymbolAddress((void**)&pq,    g_q);
    cudaGetSymbolAddress((void**)&pk,    g_k);
    cudaGetSymbolAddress((void**)&pv,    g_v);
    cudaGetSymbolAddress((void**)&pctx,  g_ctx);
    cudaGetSymbolAddress((void**)&pxt,   g_xt);
    cudaGetSymbolAddress((void**)&pwq,   g_wqt);
    cudaGetSymbolAddress((void**)&pwk,   g_wkt);
    cudaGetSymbolAddress((void**)&pwv,   g_wvt);
    cudaGetSymbolAddress((void**)&pctx3, g_ctx3);
    cudaGetSymbolAddress((void**)&pwp3,  g_wp3);

    // 1) tf32 rounding / repacking of GEMM inputs
    conv_x4_kernel<<<(Mq * Cq / 4) / 256, 256>>>((const float4*)x, (float4*)pxt);
    conv_wqkv_kernel<<<(Cq * Cq) / 256, 256>>>(Wq, pwq);
    conv_wqkv_kernel<<<(Cq * Cq) / 256, 256>>>(Wk, pwk);
    conv_wqkv_kernel<<<(Cq * Cq) / 256, 256>>>(Wv, pwv);
    conv_wp3_kernel<<<(Cq * Cq) / 256, 256>>>(Wproj, pwp3);

    // 2) Q/K/V projections on tensor cores (scatter into [B,H,T,D])
    dim3 gqkv(Cq / 128, Mq / 128);
    gemm_mma<<<gqkv, 256>>>(pxt, pwq, pq, Cq, Cq, 1, nullptr);
    gemm_mma<<<gqkv, 256>>>(pxt, pwk, pk, Cq, Cq, 1, nullptr);
    gemm_mma<<<gqkv, 256>>>(pxt, pwv, pv, Cq, Cq, 1, nullptr);

    // 3) scores (causal half only)
    dim3 gsc(Tq / 64, Tq / 64, BHq);
    scores_kernel<<<gsc, 256>>>(wei);

    // 4) softmax in place
    softmax_kernel<<<BHq * Tq, 256>>>(wei);

    // 5) ctx = P @ V  -> [B,T,C]
    dim3 gctx(Tq / 64, BHq);
    ctx_kernel<<<gctx, 256>>>(wei);

    // 6) out = ctx @ Wproj^T + b  via 2-term tf32 split (K=3072)
    conv_ctx3_kernel<<<(Mq * Cq) / 256, 256>>>(pctx, pctx3);
    dim3 gout(Cq / 128, Mq / 128);
    gemm_mma<<<gout, 256>>>(pctx3, pwp3, out, 3 * Cq, Cq, 0, bproj);
}

// round 5
// speedup vs baseline: 1.7936x; 1.2812x over previous
#include <cuda_runtime.h>
#include <math.h>
#include <stdint.h>

// Problem constants
#define Bq 8
#define Tq 1024
#define Cq 1024
#define Hq 16
#define Dq 64
#define Mq (Bq * Tq)          // 8192 rows
#define BHq (Bq * Hq)         // 128

// ---------------------------------------------------------------------------
// Scratch (device globals; no dynamic allocation allowed)
// ---------------------------------------------------------------------------
__device__ float g_q[(size_t)BHq * Tq * Dq];      // [B,H,T,D]  32 MB
__device__ float g_k[(size_t)BHq * Tq * Dq];      // 32 MB
__device__ float g_v[(size_t)BHq * Tq * Dq];      // 32 MB
__device__ float g_ctx[(size_t)Mq * Cq];          // [B,T,C]    32 MB
__device__ float g_xt[(size_t)Mq * Cq];           // x, tf32-rounded   32 MB
__device__ float g_wqt[(size_t)Cq * Cq];          // [N=HD, K=C] tf32
__device__ float g_wkt[(size_t)Cq * Cq];
__device__ float g_wvt[(size_t)Cq * Cq];
__device__ float g_ctx3[(size_t)Mq * 3 * Cq];     // split ctx [M, 3C]  96 MB
__device__ float g_wp3[(size_t)Cq * 3 * Cq];      // split Wproj [N, 3C] 12 MB

__device__ __forceinline__ float f2tf32(float a) {
    uint32_t r;
    asm("cvt.rna.tf32.f32 %0, %1;" : "=r"(r) : "f"(a));
    return __uint_as_float(r);
}

// ---------------------------------------------------------------------------
// Conversion / repack kernels
// ---------------------------------------------------------------------------
__global__ void conv_x4_kernel(const float4* __restrict__ x, float4* __restrict__ xt) {
    int i = blockIdx.x * blockDim.x + threadIdx.x;
    float4 v = x[i];
    v.x = f2tf32(v.x); v.y = f2tf32(v.y); v.z = f2tf32(v.z); v.w = f2tf32(v.w);
    xt[i] = v;
}

__global__ void conv_wqkv_kernel(const float* __restrict__ W, float* __restrict__ P) {
    int i = blockIdx.x * blockDim.x + threadIdx.x;
    int n = i >> 10;
    int c = i & 1023;
    int h = n >> 6, d = n & 63;
    P[(size_t)n * Cq + c] = f2tf32(W[((size_t)h * Cq + c) * Dq + d]);
}

__global__ void conv_wp3_kernel(const float* __restrict__ W, float* __restrict__ P) {
    int i = blockIdx.x * blockDim.x + threadIdx.x;
    int n = i >> 10;
    int c = i & 1023;
    float a  = W[(size_t)n * Cq + c];
    float hi = f2tf32(a);
    float lo = f2tf32(a - hi);
    size_t base = (size_t)n * (3 * Cq);
    P[base + c]           = hi;
    P[base + Cq + c]      = lo;
    P[base + 2 * Cq + c]  = hi;
}

__global__ void conv_ctx3_kernel(const float* __restrict__ S, float* __restrict__ P) {
    int i = blockIdx.x * blockDim.x + threadIdx.x;
    int m = i >> 10;
    int c = i & 1023;
    float a  = S[(size_t)m * Cq + c];
    float hi = f2tf32(a);
    float lo = f2tf32(a - hi);
    size_t base = (size_t)m * (3 * Cq);
    P[base + c]           = hi;
    P[base + Cq + c]      = hi;
    P[base + 2 * Cq + c]  = lo;
}

// ---------------------------------------------------------------------------
// mma helper
// ---------------------------------------------------------------------------
__device__ __forceinline__ void mma_tf32(float c[4], uint32_t a0, uint32_t a1,
                                         uint32_t a2, uint32_t a3,
                                         uint32_t b0, uint32_t b1) {
    asm volatile(
        "mma.sync.aligned.m16n8k8.row.col.f32.tf32.tf32.f32 "
        "{%0,%1,%2,%3}, {%4,%5,%6,%7}, {%8,%9}, {%0,%1,%2,%3};"
        : "+f"(c[0]), "+f"(c[1]), "+f"(c[2]), "+f"(c[3])
        : "r"(a0), "r"(a1), "r"(a2), "r"(a3), "r"(b0), "r"(b1));
}

// ---------------------------------------------------------------------------
// Warp-MMA tf32 GEMM (unchanged from R3). CTA 128x128, 256 threads.
// ---------------------------------------------------------------------------
#define SPAD 20

__global__ __launch_bounds__(256) void gemm_mma(
    const float* __restrict__ A, const float* __restrict__ Bw,
    float* __restrict__ Cout, int K, int Nout, int mode,
    const float* __restrict__ bias)
{
    __shared__ float As[128][SPAD];
    __shared__ float Bs[128][SPAD];

    const int tid  = threadIdx.x;
    const int wid  = tid >> 5;
    const int lane = tid & 31;
    const int row0 = blockIdx.y * 128;
    const int col0 = blockIdx.x * 128;
    const int wm   = (wid & 3) * 32;
    const int wn   = (wid >> 2) * 64;

    float acc[2][8][4];
#pragma unroll
    for (int mt = 0; mt < 2; mt++)
#pragma unroll
        for (int nt = 0; nt < 8; nt++)
#pragma unroll
            for (int j = 0; j < 4; j++) acc[mt][nt][j] = 0.f;

    const int r0l = tid >> 2;
    const int c4  = (tid & 3) << 2;
    const int NC = K >> 4;

    float4 ra[2], rb[2];
#pragma unroll
    for (int l = 0; l < 2; l++) {
        int r = r0l + l * 64;
        ra[l] = *(const float4*)(A  + (size_t)(row0 + r) * K + c4);
        rb[l] = *(const float4*)(Bw + (size_t)(col0 + r) * K + c4);
    }

    for (int i = 0; i < NC; i++) {
#pragma unroll
        for (int l = 0; l < 2; l++) {
            int r = r0l + l * 64;
            As[r][c4 + 0] = ra[l].x; As[r][c4 + 1] = ra[l].y;
            As[r][c4 + 2] = ra[l].z; As[r][c4 + 3] = ra[l].w;
            Bs[r][c4 + 0] = rb[l].x; Bs[r][c4 + 1] = rb[l].y;
            Bs[r][c4 + 2] = rb[l].z; Bs[r][c4 + 3] = rb[l].w;
        }
        __syncthreads();

        if (i + 1 < NC) {
            const int k0 = (i + 1) << 4;
#pragma unroll
            for (int l = 0; l < 2; l++) {
                int r = r0l + l * 64;
                ra[l] = *(const float4*)(A  + (size_t)(row0 + r) * K + k0 + c4);
                rb[l] = *(const float4*)(Bw + (size_t)(col0 + r) * K + k0 + c4);
            }
        }

#pragma unroll
        for (int ks = 0; ks < 2; ks++) {
            const int kb = ks * 8;
            const int arow = wm + (lane >> 2);
            const int acol = kb + (lane & 3);
            uint32_t af[2][4];
#pragma unroll
            for (int mt = 0; mt < 2; mt++) {
                af[mt][0] = __float_as_uint(As[arow + mt * 16    ][acol    ]);
                af[mt][1] = __float_as_uint(As[arow + mt * 16 + 8][acol    ]);
                af[mt][2] = __float_as_uint(As[arow + mt * 16    ][acol + 4]);
                af[mt][3] = __float_as_uint(As[arow + mt * 16 + 8][acol + 4]);
            }
            const int brow = wn + (lane >> 2);
            const int bcol = kb + (lane & 3);
            uint32_t bf[8][2];
#pragma unroll
            for (int nt = 0; nt < 8; nt++) {
                bf[nt][0] = __float_as_uint(Bs[brow + nt * 8][bcol    ]);
                bf[nt][1] = __float_as_uint(Bs[brow + nt * 8][bcol + 4]);
            }
#pragma unroll
            for (int mt = 0; mt < 2; mt++)
#pragma unroll
                for (int nt = 0; nt < 8; nt++)
                    mma_tf32(acc[mt][nt], af[mt][0], af[mt][1], af[mt][2], af[mt][3],
                             bf[nt][0], bf[nt][1]);
        }
        __syncthreads();
    }

    const int er = lane >> 2;
    const int ec = (lane & 3) << 1;
#pragma unroll
    for (int mt = 0; mt < 2; mt++) {
#pragma unroll
        for (int nt = 0; nt < 8; nt++) {
#pragma unroll
            for (int half = 0; half < 2; half++) {
                int m = row0 + wm + mt * 16 + er + half * 8;
#pragma unroll
                for (int j = 0; j < 2; j++) {
                    int n = col0 + wn + nt * 8 + ec + j;
                    float v = acc[mt][nt][half * 2 + j];
                    if (mode == 0) {
                        if (bias) v += bias[n];
                        Cout[(size_t)m * Nout + n] = v;
                    } else {
                        int b = m >> 10, t = m & 1023;
                        int h = n >> 6, d = n & 63;
                        Cout[((size_t)(b * Hq + h) << 16) + ((size_t)t << 6) + d] = v;
                    }
                }
            }
        }
    }
}

// ---------------------------------------------------------------------------
// Fused attention: scores + softmax + ctx, flash-style two-pass.
// Grid: (Tq/128, BHq). 256 threads = 8 warps, warp w owns rows w*16..w*16+15.
// Pass A: online row max/sum (S recomputed in pass B).
// Pass B: P = exp(S-m)/l -> smem -> wei (float4, written once); ctx += P·V.
// ---------------------------------------------------------------------------
#define AST 72   // smem row stride (floats): 72 mod 32 = 8 -> conflict-free frags

#define ATTN_SMEM_FLOATS (128 * AST + 64 * AST + 64 * AST + 128 * AST)

// compute S fragment accumulators for one 128x64 s-tile (scaled + masked)
#define COMPUTE_S(sacc, Ks_, mask_needed)                                      \
    do {                                                                       \
        _Pragma("unroll")                                                      \
        for (int nt = 0; nt < 8; nt++)                                         \
            { sacc[nt][0]=0.f; sacc[nt][1]=0.f; sacc[nt][2]=0.f; sacc[nt][3]=0.f; } \
        _Pragma("unroll")                                                      \
        for (int ks = 0; ks < 8; ks++) {                                       \
            uint32_t bf[8][2];                                                 \
            _Pragma("unroll")                                                  \
            for (int nt = 0; nt < 8; nt++) {                                   \
                int srow = nt * 8 + (lane >> 2);                               \
                int scol = ks * 8 + (lane & 3);                                \
                bf[nt][0] = __float_as_uint(Ks_[srow * AST + scol]);           \
                bf[nt][1] = __float_as_uint(Ks_[srow * AST + scol + 4]);       \
            }                                                                  \
            _Pragma("unroll")                                                  \
            for (int nt = 0; nt < 8; nt++)                                     \
                mma_tf32(sacc[nt], af[ks][0], af[ks][1], af[ks][2], af[ks][3], \
                         bf[nt][0], bf[nt][1]);                                \
        }                                                                      \
        _Pragma("unroll")                                                      \
        for (int nt = 0; nt < 8; nt++) {                                       \
            sacc[nt][0] *= 0.125f; sacc[nt][1] *= 0.125f;                      \
            sacc[nt][2] *= 0.125f; sacc[nt][3] *= 0.125f;                      \
            if (mask_needed) {                                                 \
                int s0 = sT * 64 + nt * 8 + ((lane & 3) << 1);                 \
                if (s0     > trow0) sacc[nt][0] = -INFINITY;                   \
                if (s0 + 1 > trow0) sacc[nt][1] = -INFINITY;                   \
                if (s0     > trow1) sacc[nt][2] = -INFINITY;                   \
                if (s0 + 1 > trow1) sacc[nt][3] = -INFINITY;                   \
            }                                                                  \
        }                                                                      \
    } while (0)

__global__ __launch_bounds__(256, 1) void attn_fused(float* __restrict__ wei) {
    extern __shared__ float sm[];
    float* Qs = sm;                        // [128][AST]
    float* Ks = Qs + 128 * AST;            // [64][AST]
    float* Vs = Ks + 64 * AST;             // [64][AST]
    float* Ps = Vs + 64 * AST;             // [128][AST]

    const int tid  = threadIdx.x;
    const int wid  = tid >> 5;
    const int lane = tid & 31;
    const int tB   = blockIdx.x;           // t-block (128 rows)
    const int bh   = blockIdx.y;
    const int wm   = wid * 16;             // warp row offset in tile
    const int trow0 = tB * 128 + wm + (lane >> 2);       // global t of c0/c1
    const int trow1 = trow0 + 8;                          // global t of c2/c3

    const float* qb = g_q + (size_t)bh * Tq * Dq + (size_t)tB * 128 * Dq;
    const float* kb = g_k + (size_t)bh * Tq * Dq;
    const float* vb = g_v + (size_t)bh * Tq * Dq;
    float* wb = wei + (size_t)bh * Tq * Tq + (size_t)tB * 128 * Tq;

    // ---- load Q tile (tf32-rounded) ----
#pragma unroll
    for (int l = 0; l < 8; l++) {
        int f = tid + l * 256;
        int r = f >> 4, c4 = (f & 15) << 2;
        float4 v = *(const float4*)(qb + (size_t)r * Dq + c4);
        Qs[r * AST + c4 + 0] = f2tf32(v.x);
        Qs[r * AST + c4 + 1] = f2tf32(v.y);
        Qs[r * AST + c4 + 2] = f2tf32(v.z);
        Qs[r * AST + c4 + 3] = f2tf32(v.w);
    }
    __syncthreads();

    // ---- persistent Q fragments ----
    uint32_t af[8][4];
    {
        const int arow = wm + (lane >> 2);
#pragma unroll
        for (int ks = 0; ks < 8; ks++) {
            const int acol = ks * 8 + (lane & 3);
            af[ks][0] = __float_as_uint(Qs[(arow    ) * AST + acol    ]);
            af[ks][1] = __float_as_uint(Qs[(arow + 8) * AST + acol    ]);
            af[ks][2] = __float_as_uint(Qs[(arow    ) * AST + acol + 4]);
            af[ks][3] = __float_as_uint(Qs[(arow + 8) * AST + acol + 4]);
        }
    }

    const int nS = 2 * tB + 2;             // s-tiles covering causal region

    float m0 = -INFINITY, m1 = -INFINITY, l0 = 0.f, l1 = 0.f;

    // =================== Pass A: stats ===================
    for (int sT = 0; sT < nS; sT++) {
        // load K tile (tf32)
#pragma unroll
        for (int l = 0; l < 4; l++) {
            int f = tid + l * 256;
            int r = f >> 4, c4 = (f & 15) << 2;
            float4 v = *(const float4*)(kb + (size_t)(sT * 64 + r) * Dq + c4);
            Ks[r * AST + c4 + 0] = f2tf32(v.x);
            Ks[r * AST + c4 + 1] = f2tf32(v.y);
            Ks[r * AST + c4 + 2] = f2tf32(v.z);
            Ks[r * AST + c4 + 3] = f2tf32(v.w);
        }
        __syncthreads();

        float sacc[8][4];
        const bool mask = (sT >= 2 * tB);
        COMPUTE_S(sacc, Ks, mask);

        // row max over this tile
        float tm0 = -INFINITY, tm1 = -INFINITY;
#pragma unroll
        for (int nt = 0; nt < 8; nt++) {
            tm0 = fmaxf(tm0, fmaxf(sacc[nt][0], sacc[nt][1]));
            tm1 = fmaxf(tm1, fmaxf(sacc[nt][2], sacc[nt][3]));
        }
        tm0 = fmaxf(tm0, __shfl_xor_sync(0xffffffffu, tm0, 1));
        tm0 = fmaxf(tm0, __shfl_xor_sync(0xffffffffu, tm0, 2));
        tm1 = fmaxf(tm1, __shfl_xor_sync(0xffffffffu, tm1, 1));
        tm1 = fmaxf(tm1, __shfl_xor_sync(0xffffffffu, tm1, 2));

        float m0n = fmaxf(m0, tm0);
        float m1n = fmaxf(m1, tm1);
        float s0 = 0.f, s1 = 0.f;
#pragma unroll
        for (int nt = 0; nt < 8; nt++) {
            s0 += __expf(sacc[nt][0] - m0n) + __expf(sacc[nt][1] - m0n);
            s1 += __expf(sacc[nt][2] - m1n) + __expf(sacc[nt][3] - m1n);
        }
        s0 += __shfl_xor_sync(0xffffffffu, s0, 1);
        s0 += __shfl_xor_sync(0xffffffffu, s0, 2);
        s1 += __shfl_xor_sync(0xffffffffu, s1, 1);
        s1 += __shfl_xor_sync(0xffffffffu, s1, 2);

        l0 = l0 * __expf(m0 - m0n) + s0;  m0 = m0n;
        l1 = l1 * __expf(m1 - m1n) + s1;  m1 = m1n;
        __syncthreads();
    }

    const float inv0 = 1.0f / l0;
    const float inv1 = 1.0f / l1;

    // =================== Pass B: P -> wei, ctx += P·V ===================
    float ctx[8][4];
#pragma unroll
    for (int nt = 0; nt < 8; nt++)
        { ctx[nt][0]=0.f; ctx[nt][1]=0.f; ctx[nt][2]=0.f; ctx[nt][3]=0.f; }

    for (int sT = 0; sT < nS; sT++) {
        // load K + V tiles (tf32)
#pragma unroll
        for (int l = 0; l < 4; l++) {
            int f = tid + l * 256;
            int r = f >> 4, c4 = (f & 15) << 2;
            float4 v = *(const float4*)(kb + (size_t)(sT * 64 + r) * Dq + c4);
            Ks[r * AST + c4 + 0] = f2tf32(v.x);
            Ks[r * AST + c4 + 1] = f2tf32(v.y);
            Ks[r * AST + c4 + 2] = f2tf32(v.z);
            Ks[r * AST + c4 + 3] = f2tf32(v.w);
            float4 w = *(const float4*)(vb + (size_t)(sT * 64 + r) * Dq + c4);
            Vs[r * AST + c4 + 0] = f2tf32(w.x);
            Vs[r * AST + c4 + 1] = f2tf32(w.y);
            Vs[r * AST + c4 + 2] = f2tf32(w.z);
            Vs[r * AST + c4 + 3] = f2tf32(w.w);
        }
        __syncthreads();

        float sacc[8][4];
        const bool mask = (sT >= 2 * tB);
        COMPUTE_S(sacc, Ks, mask);

        // P = exp(S - m) / l ; stage into Ps
        {
            const int pr = wm + (lane >> 2);
            const int pc = (lane & 3) << 1;
#pragma unroll
            for (int nt = 0; nt < 8; nt++) {
                float p0 = __expf(sacc[nt][0] - m0) * inv0;
                float p1 = __expf(sacc[nt][1] - m0) * inv0;
                float p2 = __expf(sacc[nt][2] - m1) * inv1;
                float p3 = __expf(sacc[nt][3] - m1) * inv1;
                Ps[(pr    ) * AST + nt * 8 + pc    ] = p0;
                Ps[(pr    ) * AST + nt * 8 + pc + 1] = p1;
                Ps[(pr + 8) * AST + nt * 8 + pc    ] = p2;
                Ps[(pr + 8) * AST + nt * 8 + pc + 1] = p3;
            }
        }
        __syncthreads();

        // write P tile to wei (coalesced float4, written exactly once)
#pragma unroll
        for (int l = 0; l < 8; l++) {
            int f = tid + l * 256;
            int r = f >> 4, c4 = (f & 15) << 2;
            *(float4*)(wb + (size_t)r * Tq + sT * 64 + c4) = *(const float4*)(Ps + r * AST + c4);
        }

        // ctx += P·V
#pragma unroll
        for (int ks = 0; ks < 8; ks++) {
            const int arow = wm + (lane >> 2);
            const int acol = ks * 8 + (lane & 3);
            uint32_t ap[4];
            ap[0] = __float_as_uint(f2tf32(Ps[(arow    ) * AST + acol    ]));
            ap[1] = __float_as_uint(f2tf32(Ps[(arow + 8) * AST + acol    ]));
            ap[2] = __float_as_uint(f2tf32(Ps[(arow    ) * AST + acol + 4]));
            ap[3] = __float_as_uint(f2tf32(Ps[(arow + 8) * AST + acol + 4]));
            uint32_t bv[8][2];
#pragma unroll
            for (int nt = 0; nt < 8; nt++) {
                int vrow = ks * 8 + (lane & 3);
                int vcol = nt * 8 + (lane >> 2);
                bv[nt][0] = __float_as_uint(Vs[(vrow    ) * AST + vcol]);
                bv[nt][1] = __float_as_uint(Vs[(vrow + 4) * AST + vcol]);
            }
#pragma unroll
            for (int nt = 0; nt < 8; nt++)
                mma_tf32(ctx[nt], ap[0], ap[1], ap[2], ap[3], bv[nt][0], bv[nt][1]);
        }
        __syncthreads();
    }

    // zero-fill upper triangle region (cols >= nS*64)
    {
        const int nz4 = (16 - nS) * 16;            // zero float4s per row
        if (nz4 > 0) {
            const float4 z = {0.f, 0.f, 0.f, 0.f};
            for (int f = tid; f < 128 * nz4; f += 256) {
                int r  = f / nz4;
                int c4 = (f - r * nz4) << 2;
                *(float4*)(wb + (size_t)r * Tq + nS * 64 + c4) = z;
            }
        }
    }

    // write ctx -> g_ctx [B,T,C]
    {
        const int b = bh >> 4, h = bh & 15;
        const int ec = (lane & 3) << 1;
#pragma unroll
        for (int nt = 0; nt < 8; nt++) {
            float2 v0 = {ctx[nt][0], ctx[nt][1]};
            float2 v1 = {ctx[nt][2], ctx[nt][3]};
            int c = h * 64 + nt * 8 + ec;
            *(float2*)(g_ctx + ((size_t)(b * Tq + trow0) << 10) + c) = v0;
            *(float2*)(g_ctx + ((size_t)(b * Tq + trow1) << 10) + c) = v1;
        }
    }
}

// ---------------------------------------------------------------------------
// Launch
// ---------------------------------------------------------------------------
extern "C" void kernel_launch(void* const* d_in, const int* in_sizes, int n_in,
                              void* d_out, int out_size) {
    const float* x     = (const float*)d_in[0];
    const float* Wq    = (const float*)d_in[1];
    const float* Wk    = (const float*)d_in[2];
    const float* Wv    = (const float*)d_in[3];
    const float* Wproj = (const float*)d_in[4];
    const float* bproj = (const float*)d_in[5];

    float* out = (float*)d_out;                       // [B,T,C]
    float* wei = out + (size_t)Bq * Tq * Cq;          // [B,H,T,T]

    float *pq, *pk, *pv, *pctx, *pxt, *pwq, *pwk, *pwv, *pctx3, *pwp3;
    cudaGetSymbolAddress((void**)&pq,    g_q);
    cudaGetSymbolAddress((void**)&pk,    g_k);
    cudaGetSymbolAddress((void**)&pv,    g_v);
    cudaGetSymbolAddress((void**)&pctx,  g_ctx);
    cudaGetSymbolAddress((void**)&pxt,   g_xt);
    cudaGetSymbolAddress((void**)&pwq,   g_wqt);
    cudaGetSymbolAddress((void**)&pwk,   g_wkt);
    cudaGetSymbolAddress((void**)&pwv,   g_wvt);
    cudaGetSymbolAddress((void**)&pctx3, g_ctx3);
    cudaGetSymbolAddress((void**)&pwp3,  g_wp3);

    const int attn_smem = ATTN_SMEM_FLOATS * 4;
    cudaFuncSetAttribute(attn_fused, cudaFuncAttributeMaxDynamicSharedMemorySize, attn_smem);

    // 1) tf32 rounding / repacking of GEMM inputs
    conv_x4_kernel<<<(Mq * Cq / 4) / 256, 256>>>((const float4*)x, (float4*)pxt);
    conv_wqkv_kernel<<<(Cq * Cq) / 256, 256>>>(Wq, pwq);
    conv_wqkv_kernel<<<(Cq * Cq) / 256, 256>>>(Wk, pwk);
    conv_wqkv_kernel<<<(Cq * Cq) / 256, 256>>>(Wv, pwv);
    conv_wp3_kernel<<<(Cq * Cq) / 256, 256>>>(Wproj, pwp3);

    // 2) Q/K/V projections on tensor cores (scatter into [B,H,T,D])
    dim3 gqkv(Cq / 128, Mq / 128);
    gemm_mma<<<gqkv, 256>>>(pxt, pwq, pq, Cq, Cq, 1, nullptr);
    gemm_mma<<<gqkv, 256>>>(pxt, pwk, pk, Cq, Cq, 1, nullptr);
    gemm_mma<<<gqkv, 256>>>(pxt, pwv, pv, Cq, Cq, 1, nullptr);

    // 3-5) fused scores + softmax + ctx
    dim3 gattn(Tq / 128, BHq);
    attn_fused<<<gattn, 256, attn_smem>>>(wei);

    // 6) out = ctx @ Wproj^T + b  via 2-term tf32 split (K=3072)
    conv_ctx3_kernel<<<(Mq * Cq) / 256, 256>>>(pctx, pctx3);
    dim3 gout(Cq / 128, Mq / 128);
    gemm_mma<<<gout, 256>>>(pctx3, pwp3, out, 3 * Cq, Cq, 0, bproj);
}

// round 6
// speedup vs baseline: 2.4600x; 1.3715x over previous
#include <cuda_runtime.h>
#include <math.h>
#include <stdint.h>

// Problem constants
#define Bq 8
#define Tq 1024
#define Cq 1024
#define Hq 16
#define Dq 64
#define Mq (Bq * Tq)          // 8192 rows
#define BHq (Bq * Hq)         // 128

// ---------------------------------------------------------------------------
// Scratch (device globals; no dynamic allocation allowed)
// ---------------------------------------------------------------------------
__device__ float g_q[(size_t)BHq * Tq * Dq];      // [B,H,T,D]  32 MB
__device__ float g_k[(size_t)BHq * Tq * Dq];      // 32 MB
__device__ float g_v[(size_t)BHq * Tq * Dq];      // 32 MB
__device__ float g_ctx[(size_t)Mq * Cq];          // [B,T,C]    32 MB
__device__ float g_xt[(size_t)Mq * Cq];           // x, tf32-rounded   32 MB
__device__ float g_wqkv[(size_t)3 * Cq * Cq];     // packed [3][N=HD][K=C] tf32
__device__ float g_ctx2[(size_t)Mq * 2 * Cq];     // split ctx [M, 2C]  64 MB
__device__ float g_wp2[(size_t)Cq * 2 * Cq];      // Wproj tf32 [N, 2C]  8 MB

__device__ __forceinline__ float f2tf32(float a) {
    uint32_t r;
    asm("cvt.rna.tf32.f32 %0, %1;" : "=r"(r) : "f"(a));
    return __uint_as_float(r);
}
__device__ __forceinline__ uint32_t smem_u32(const void* p) {
    uint32_t a;
    asm("{ .reg .u64 t; cvta.to.shared.u64 t, %1; cvt.u32.u64 %0, t; }" : "=r"(a) : "l"(p));
    return a;
}

// ---------------------------------------------------------------------------
// Conversion / repack kernels
// ---------------------------------------------------------------------------
__global__ void conv_x4_kernel(const float4* __restrict__ x, float4* __restrict__ xt) {
    int i = blockIdx.x * blockDim.x + threadIdx.x;
    float4 v = x[i];
    v.x = f2tf32(v.x); v.y = f2tf32(v.y); v.z = f2tf32(v.z); v.w = f2tf32(v.w);
    xt[i] = v;
}

// W [H,C,D] -> dst [N=HD, K=C], tf32-rounded
__global__ void conv_wqkv_kernel(const float* __restrict__ W, float* __restrict__ P) {
    int i = blockIdx.x * blockDim.x + threadIdx.x;
    int n = i >> 10;
    int c = i & 1023;
    int h = n >> 6, d = n & 63;
    P[(size_t)n * Cq + c] = f2tf32(W[((size_t)h * Cq + c) * Dq + d]);
}

// Wproj [N,K] -> [N, 2K]: (hi | hi)
__global__ void conv_wp2_kernel(const float* __restrict__ W, float* __restrict__ P) {
    int i = blockIdx.x * blockDim.x + threadIdx.x;
    int n = i >> 10;
    int c = i & 1023;
    float hi = f2tf32(W[(size_t)n * Cq + c]);
    size_t base = (size_t)n * (2 * Cq);
    P[base + c]      = hi;
    P[base + Cq + c] = hi;
}

// ctx [M,C] -> [M, 2C]: (hi | lo)
__global__ void conv_ctx2_kernel(const float* __restrict__ S, float* __restrict__ P) {
    int i = blockIdx.x * blockDim.x + threadIdx.x;
    int m = i >> 10;
    int c = i & 1023;
    float a  = S[(size_t)m * Cq + c];
    float hi = f2tf32(a);
    float lo = f2tf32(a - hi);
    size_t base = (size_t)m * (2 * Cq);
    P[base + c]      = hi;
    P[base + Cq + c] = lo;
}

// ---------------------------------------------------------------------------
// mma helper
// ---------------------------------------------------------------------------
__device__ __forceinline__ void mma_tf32(float c[4], uint32_t a0, uint32_t a1,
                                         uint32_t a2, uint32_t a3,
                                         uint32_t b0, uint32_t b1) {
    asm volatile(
        "mma.sync.aligned.m16n8k8.row.col.f32.tf32.tf32.f32 "
        "{%0,%1,%2,%3}, {%4,%5,%6,%7}, {%8,%9}, {%0,%1,%2,%3};"
        : "+f"(c[0]), "+f"(c[1]), "+f"(c[2]), "+f"(c[3])
        : "r"(a0), "r"(a1), "r"(a2), "r"(a3), "r"(b0), "r"(b1));
}

// ---------------------------------------------------------------------------
// cp.async double-buffered warp-MMA tf32 GEMM.
// CTA tile 128x128, K-chunk 32, 256 threads (8 warps 4x2, warp tile 32x64).
// A [Mtot,K] row-major; B [Ntot,K] row-major (computes A·B^T).
// mode 0: Cout = acc (+bias); mode 1: scatter to [B,H,T,D], z selects out/W.
// ---------------------------------------------------------------------------
#define GST 36                       // smem row stride (floats)
#define STGF (2 * 128 * GST)         // floats per stage (A + B)
#define GEMM_SMEM_BYTES (2 * STGF * 4)

__global__ __launch_bounds__(256) void gemm_mma2(
    const float* __restrict__ A, const float* __restrict__ BwBase,
    float* __restrict__ O0, float* __restrict__ O1, float* __restrict__ O2,
    int K, int Nout, int mode, const float* __restrict__ bias)
{
    extern __shared__ float smem[];
    const float* Bw = BwBase + ((mode == 1) ? (size_t)blockIdx.z * Cq * Cq : 0);
    float* Cout = (mode == 1) ? (blockIdx.z == 0 ? O0 : blockIdx.z == 1 ? O1 : O2) : O0;

    const int tid  = threadIdx.x;
    const int wid  = tid >> 5;
    const int lane = tid & 31;
    const int row0 = blockIdx.y * 128;
    const int col0 = blockIdx.x * 128;
    const int wm   = (wid & 3) * 32;
    const int wn   = (wid >> 2) * 64;
    const uint32_t smb = smem_u32(smem);

    // load geometry: 4 float4 slots each for A and B per stage
    int lrow[4], lc4[4];
#pragma unroll
    for (int l = 0; l < 4; l++) {
        int idx = l * 256 + tid;
        lrow[l] = idx >> 3;
        lc4[l]  = (idx & 7) << 2;
    }

    const int NC = K >> 5;

#define ISSUE_STAGE(s)                                                          \
    do {                                                                        \
        const int k0 = (s) << 5;                                                \
        const uint32_t sb = smb + ((s) & 1) * (STGF * 4);                       \
        _Pragma("unroll")                                                       \
        for (int l = 0; l < 4; l++) {                                           \
            uint32_t da = sb + (uint32_t)(lrow[l] * GST + lc4[l]) * 4;          \
            const float* sa = A + (size_t)(row0 + lrow[l]) * K + k0 + lc4[l];   \
            asm volatile("cp.async.cg.shared.global [%0], [%1], 16;"            \
                         :: "r"(da), "l"(sa));                                  \
            uint32_t db = sb + (uint32_t)(128 * GST + lrow[l] * GST + lc4[l]) * 4; \
            const float* sbp = Bw + (size_t)(col0 + lrow[l]) * K + k0 + lc4[l]; \
            asm volatile("cp.async.cg.shared.global [%0], [%1], 16;"            \
                         :: "r"(db), "l"(sbp));                                 \
        }                                                                       \
        asm volatile("cp.async.commit_group;");                                 \
    } while (0)

    float acc[2][8][4];
#pragma unroll
    for (int mt = 0; mt < 2; mt++)
#pragma unroll
        for (int nt = 0; nt < 8; nt++)
#pragma unroll
            for (int j = 0; j < 4; j++) acc[mt][nt][j] = 0.f;

    // prologue: stages 0 and 1
    ISSUE_STAGE(0);
    if (1 < NC) ISSUE_STAGE(1); else asm volatile("cp.async.commit_group;");

    for (int i = 0; i < NC; i++) {
        asm volatile("cp.async.wait_group 1;");
        __syncthreads();

        const float* As_ = smem + (i & 1) * STGF;
        const float* Bs_ = As_ + 128 * GST;

#pragma unroll
        for (int ks = 0; ks < 4; ks++) {
            const int kb = ks * 8;
            const int arow = wm + (lane >> 2);
            const int acol = kb + (lane & 3);
            uint32_t af[2][4];
#pragma unroll
            for (int mt = 0; mt < 2; mt++) {
                af[mt][0] = __float_as_uint(As_[(arow + mt * 16    ) * GST + acol    ]);
                af[mt][1] = __float_as_uint(As_[(arow + mt * 16 + 8) * GST + acol    ]);
                af[mt][2] = __float_as_uint(As_[(arow + mt * 16    ) * GST + acol + 4]);
                af[mt][3] = __float_as_uint(As_[(arow + mt * 16 + 8) * GST + acol + 4]);
            }
            const int brow = wn + (lane >> 2);
            const int bcol = kb + (lane & 3);
            uint32_t bf[8][2];
#pragma unroll
            for (int nt = 0; nt < 8; nt++) {
                bf[nt][0] = __float_as_uint(Bs_[(brow + nt * 8) * GST + bcol    ]);
                bf[nt][1] = __float_as_uint(Bs_[(brow + nt * 8) * GST + bcol + 4]);
            }
#pragma unroll
            for (int mt = 0; mt < 2; mt++)
#pragma unroll
                for (int nt = 0; nt < 8; nt++)
                    mma_tf32(acc[mt][nt], af[mt][0], af[mt][1], af[mt][2], af[mt][3],
                             bf[nt][0], bf[nt][1]);
        }
        __syncthreads();

        if (i + 2 < NC) ISSUE_STAGE(i + 2);
        else asm volatile("cp.async.commit_group;");
    }

    const int er = lane >> 2;
    const int ec = (lane & 3) << 1;
#pragma unroll
    for (int mt = 0; mt < 2; mt++) {
#pragma unroll
        for (int nt = 0; nt < 8; nt++) {
#pragma unroll
            for (int half = 0; half < 2; half++) {
                int m = row0 + wm + mt * 16 + er + half * 8;
#pragma unroll
                for (int j = 0; j < 2; j++) {
                    int n = col0 + wn + nt * 8 + ec + j;
                    float v = acc[mt][nt][half * 2 + j];
                    if (mode == 0) {
                        if (bias) v += bias[n];
                        Cout[(size_t)m * Nout + n] = v;
                    } else {
                        int b = m >> 10, t = m & 1023;
                        int h = n >> 6, d = n & 63;
                        Cout[((size_t)(b * Hq + h) << 16) + ((size_t)t << 6) + d] = v;
                    }
                }
            }
        }
    }
#undef ISSUE_STAGE
}

// ---------------------------------------------------------------------------
// Fused attention: scores + softmax + ctx, flash-style two-pass (as R4).
// ---------------------------------------------------------------------------
#define AST 72
#define ATTN_SMEM_FLOATS (128 * AST + 64 * AST + 64 * AST + 128 * AST)

#define COMPUTE_S(sacc, Ks_, mask_needed)                                      \
    do {                                                                       \
        _Pragma("unroll")                                                      \
        for (int nt = 0; nt < 8; nt++)                                         \
            { sacc[nt][0]=0.f; sacc[nt][1]=0.f; sacc[nt][2]=0.f; sacc[nt][3]=0.f; } \
        _Pragma("unroll")                                                      \
        for (int ks = 0; ks < 8; ks++) {                                       \
            uint32_t bf[8][2];                                                 \
            _Pragma("unroll")                                                  \
            for (int nt = 0; nt < 8; nt++) {                                   \
                int srow = nt * 8 + (lane >> 2);                               \
                int scol = ks * 8 + (lane & 3);                                \
                bf[nt][0] = __float_as_uint(Ks_[srow * AST + scol]);           \
                bf[nt][1] = __float_as_uint(Ks_[srow * AST + scol + 4]);       \
            }                                                                  \
            _Pragma("unroll")                                                  \
            for (int nt = 0; nt < 8; nt++)                                     \
                mma_tf32(sacc[nt], af[ks][0], af[ks][1], af[ks][2], af[ks][3], \
                         bf[nt][0], bf[nt][1]);                                \
        }                                                                      \
        _Pragma("unroll")                                                      \
        for (int nt = 0; nt < 8; nt++) {                                       \
            sacc[nt][0] *= 0.125f; sacc[nt][1] *= 0.125f;                      \
            sacc[nt][2] *= 0.125f; sacc[nt][3] *= 0.125f;                      \
            if (mask_needed) {                                                 \
                int s0 = sT * 64 + nt * 8 + ((lane & 3) << 1);                 \
                if (s0     > trow0) sacc[nt][0] = -INFINITY;                   \
                if (s0 + 1 > trow0) sacc[nt][1] = -INFINITY;                   \
                if (s0     > trow1) sacc[nt][2] = -INFINITY;                   \
                if (s0 + 1 > trow1) sacc[nt][3] = -INFINITY;                   \
            }                                                                  \
        }                                                                      \
    } while (0)

__global__ __launch_bounds__(256, 1) void attn_fused(float* __restrict__ wei) {
    extern __shared__ float sm[];
    float* Qs = sm;
    float* Ks = Qs + 128 * AST;
    float* Vs = Ks + 64 * AST;
    float* Ps = Vs + 64 * AST;

    const int tid  = threadIdx.x;
    const int wid  = tid >> 5;
    const int lane = tid & 31;
    const int tB   = blockIdx.x;
    const int bh   = blockIdx.y;
    const int wm   = wid * 16;
    const int trow0 = tB * 128 + wm + (lane >> 2);
    const int trow1 = trow0 + 8;

    const float* qb = g_q + (size_t)bh * Tq * Dq + (size_t)tB * 128 * Dq;
    const float* kb = g_k + (size_t)bh * Tq * Dq;
    const float* vb = g_v + (size_t)bh * Tq * Dq;
    float* wb = wei + (size_t)bh * Tq * Tq + (size_t)tB * 128 * Tq;

#pragma unroll
    for (int l = 0; l < 8; l++) {
        int f = tid + l * 256;
        int r = f >> 4, c4 = (f & 15) << 2;
        float4 v = *(const float4*)(qb + (size_t)r * Dq + c4);
        Qs[r * AST + c4 + 0] = f2tf32(v.x);
        Qs[r * AST + c4 + 1] = f2tf32(v.y);
        Qs[r * AST + c4 + 2] = f2tf32(v.z);
        Qs[r * AST + c4 + 3] = f2tf32(v.w);
    }
    __syncthreads();

    uint32_t af[8][4];
    {
        const int arow = wm + (lane >> 2);
#pragma unroll
        for (int ks = 0; ks < 8; ks++) {
            const int acol = ks * 8 + (lane & 3);
            af[ks][0] = __float_as_uint(Qs[(arow    ) * AST + acol    ]);
            af[ks][1] = __float_as_uint(Qs[(arow + 8) * AST + acol    ]);
            af[ks][2] = __float_as_uint(Qs[(arow    ) * AST + acol + 4]);
            af[ks][3] = __float_as_uint(Qs[(arow + 8) * AST + acol + 4]);
        }
    }

    const int nS = 2 * tB + 2;
    float m0 = -INFINITY, m1 = -INFINITY, l0 = 0.f, l1 = 0.f;

    // Pass A
    for (int sT = 0; sT < nS; sT++) {
#pragma unroll
        for (int l = 0; l < 4; l++) {
            int f = tid + l * 256;
            int r = f >> 4, c4 = (f & 15) << 2;
            float4 v = *(const float4*)(kb + (size_t)(sT * 64 + r) * Dq + c4);
            Ks[r * AST + c4 + 0] = f2tf32(v.x);
            Ks[r * AST + c4 + 1] = f2tf32(v.y);
            Ks[r * AST + c4 + 2] = f2tf32(v.z);
            Ks[r * AST + c4 + 3] = f2tf32(v.w);
        }
        __syncthreads();

        float sacc[8][4];
        const bool mask = (sT >= 2 * tB);
        COMPUTE_S(sacc, Ks, mask);

        float tm0 = -INFINITY, tm1 = -INFINITY;
#pragma unroll
        for (int nt = 0; nt < 8; nt++) {
            tm0 = fmaxf(tm0, fmaxf(sacc[nt][0], sacc[nt][1]));
            tm1 = fmaxf(tm1, fmaxf(sacc[nt][2], sacc[nt][3]));
        }
        tm0 = fmaxf(tm0, __shfl_xor_sync(0xffffffffu, tm0, 1));
        tm0 = fmaxf(tm0, __shfl_xor_sync(0xffffffffu, tm0, 2));
        tm1 = fmaxf(tm1, __shfl_xor_sync(0xffffffffu, tm1, 1));
        tm1 = fmaxf(tm1, __shfl_xor_sync(0xffffffffu, tm1, 2));

        float m0n = fmaxf(m0, tm0);
        float m1n = fmaxf(m1, tm1);
        float s0 = 0.f, s1 = 0.f;
#pragma unroll
        for (int nt = 0; nt < 8; nt++) {
            s0 += __expf(sacc[nt][0] - m0n) + __expf(sacc[nt][1] - m0n);
            s1 += __expf(sacc[nt][2] - m1n) + __expf(sacc[nt][3] - m1n);
        }
        s0 += __shfl_xor_sync(0xffffffffu, s0, 1);
        s0 += __shfl_xor_sync(0xffffffffu, s0, 2);
        s1 += __shfl_xor_sync(0xffffffffu, s1, 1);
        s1 += __shfl_xor_sync(0xffffffffu, s1, 2);

        l0 = l0 * __expf(m0 - m0n) + s0;  m0 = m0n;
        l1 = l1 * __expf(m1 - m1n) + s1;  m1 = m1n;
        __syncthreads();
    }

    const float inv0 = 1.0f / l0;
    const float inv1 = 1.0f / l1;

    // Pass B
    float ctx[8][4];
#pragma unroll
    for (int nt = 0; nt < 8; nt++)
        { ctx[nt][0]=0.f; ctx[nt][1]=0.f; ctx[nt][2]=0.f; ctx[nt][3]=0.f; }

    for (int sT = 0; sT < nS; sT++) {
#pragma unroll
        for (int l = 0; l < 4; l++) {
            int f = tid + l * 256;
            int r = f >> 4, c4 = (f & 15) << 2;
            float4 v = *(const float4*)(kb + (size_t)(sT * 64 + r) * Dq + c4);
            Ks[r * AST + c4 + 0] = f2tf32(v.x);
            Ks[r * AST + c4 + 1] = f2tf32(v.y);
            Ks[r * AST + c4 + 2] = f2tf32(v.z);
            Ks[r * AST + c4 + 3] = f2tf32(v.w);
            float4 w = *(const float4*)(vb + (size_t)(sT * 64 + r) * Dq + c4);
            Vs[r * AST + c4 + 0] = f2tf32(w.x);
            Vs[r * AST + c4 + 1] = f2tf32(w.y);
            Vs[r * AST + c4 + 2] = f2tf32(w.z);
            Vs[r * AST + c4 + 3] = f2tf32(w.w);
        }
        __syncthreads();

        float sacc[8][4];
        const bool mask = (sT >= 2 * tB);
        COMPUTE_S(sacc, Ks, mask);

        {
            const int pr = wm + (lane >> 2);
            const int pc = (lane & 3) << 1;
#pragma unroll
            for (int nt = 0; nt < 8; nt++) {
                float p0 = __expf(sacc[nt][0] - m0) * inv0;
                float p1 = __expf(sacc[nt][1] - m0) * inv0;
                float p2 = __expf(sacc[nt][2] - m1) * inv1;
                float p3 = __expf(sacc[nt][3] - m1) * inv1;
                Ps[(pr    ) * AST + nt * 8 + pc    ] = p0;
                Ps[(pr    ) * AST + nt * 8 + pc + 1] = p1;
                Ps[(pr + 8) * AST + nt * 8 + pc    ] = p2;
                Ps[(pr + 8) * AST + nt * 8 + pc + 1] = p3;
            }
        }
        __syncthreads();

#pragma unroll
        for (int l = 0; l < 8; l++) {
            int f = tid + l * 256;
            int r = f >> 4, c4 = (f & 15) << 2;
            *(float4*)(wb + (size_t)r * Tq + sT * 64 + c4) = *(const float4*)(Ps + r * AST + c4);
        }

#pragma unroll
        for (int ks = 0; ks < 8; ks++) {
            const int arow = wm + (lane >> 2);
            const int acol = ks * 8 + (lane & 3);
            uint32_t ap[4];
            ap[0] = __float_as_uint(f2tf32(Ps[(arow    ) * AST + acol    ]));
            ap[1] = __float_as_uint(f2tf32(Ps[(arow + 8) * AST + acol    ]));
            ap[2] = __float_as_uint(f2tf32(Ps[(arow    ) * AST + acol + 4]));
            ap[3] = __float_as_uint(f2tf32(Ps[(arow + 8) * AST + acol + 4]));
            uint32_t bv[8][2];
#pragma unroll
            for (int nt = 0; nt < 8; nt++) {
                int vrow = ks * 8 + (lane & 3);
                int vcol = nt * 8 + (lane >> 2);
                bv[nt][0] = __float_as_uint(Vs[(vrow    ) * AST + vcol]);
                bv[nt][1] = __float_as_uint(Vs[(vrow + 4) * AST + vcol]);
            }
#pragma unroll
            for (int nt = 0; nt < 8; nt++)
                mma_tf32(ctx[nt], ap[0], ap[1], ap[2], ap[3], bv[nt][0], bv[nt][1]);
        }
        __syncthreads();
    }

    {
        const int nz4 = (16 - nS) * 16;
        if (nz4 > 0) {
            const float4 z = {0.f, 0.f, 0.f, 0.f};
            for (int f = tid; f < 128 * nz4; f += 256) {
                int r  = f / nz4;
                int c4 = (f - r * nz4) << 2;
                *(float4*)(wb + (size_t)r * Tq + nS * 64 + c4) = z;
            }
        }
    }

    {
        const int b = bh >> 4, h = bh & 15;
        const int ec = (lane & 3) << 1;
#pragma unroll
        for (int nt = 0; nt < 8; nt++) {
            float2 v0 = {ctx[nt][0], ctx[nt][1]};
            float2 v1 = {ctx[nt][2], ctx[nt][3]};
            int c = h * 64 + nt * 8 + ec;
            *(float2*)(g_ctx + ((size_t)(b * Tq + trow0) << 10) + c) = v0;
            *(float2*)(g_ctx + ((size_t)(b * Tq + trow1) << 10) + c) = v1;
        }
    }
}

// ---------------------------------------------------------------------------
// Launch
// ---------------------------------------------------------------------------
extern "C" void kernel_launch(void* const* d_in, const int* in_sizes, int n_in,
                              void* d_out, int out_size) {
    const float* x     = (const float*)d_in[0];
    const float* Wq    = (const float*)d_in[1];
    const float* Wk    = (const float*)d_in[2];
    const float* Wv    = (const float*)d_in[3];
    const float* Wproj = (const float*)d_in[4];
    const float* bproj = (const float*)d_in[5];

    float* out = (float*)d_out;                       // [B,T,C]
    float* wei = out + (size_t)Bq * Tq * Cq;          // [B,H,T,T]

    float *pq, *pk, *pv, *pctx, *pxt, *pwqkv, *pctx2, *pwp2;
    cudaGetSymbolAddress((void**)&pq,    g_q);
    cudaGetSymbolAddress((void**)&pk,    g_k);
    cudaGetSymbolAddress((void**)&pv,    g_v);
    cudaGetSymbolAddress((void**)&pctx,  g_ctx);
    cudaGetSymbolAddress((void**)&pxt,   g_xt);
    cudaGetSymbolAddress((void**)&pwqkv, g_wqkv);
    cudaGetSymbolAddress((void**)&pctx2, g_ctx2);
    cudaGetSymbolAddress((void**)&pwp2,  g_wp2);

    const int attn_smem = ATTN_SMEM_FLOATS * 4;
    cudaFuncSetAttribute(attn_fused, cudaFuncAttributeMaxDynamicSharedMemorySize, attn_smem);
    cudaFuncSetAttribute(gemm_mma2, cudaFuncAttributeMaxDynamicSharedMemorySize, GEMM_SMEM_BYTES);

    // 1) tf32 rounding / repacking of GEMM inputs
    conv_x4_kernel<<<(Mq * Cq / 4) / 256, 256>>>((const float4*)x, (float4*)pxt);
    conv_wqkv_kernel<<<(Cq * Cq) / 256, 256>>>(Wq, pwqkv);
    conv_wqkv_kernel<<<(Cq * Cq) / 256, 256>>>(Wk, pwqkv + (size_t)Cq * Cq);
    conv_wqkv_kernel<<<(Cq * Cq) / 256, 256>>>(Wv, pwqkv + (size_t)2 * Cq * Cq);
    conv_wp2_kernel<<<(Cq * Cq) / 256, 256>>>(Wproj, pwp2);

    // 2) Q/K/V projections: one z=3 grid on tensor cores (scatter to [B,H,T,D])
    dim3 gqkv(Cq / 128, Mq / 128, 3);
    gemm_mma2<<<gqkv, 256, GEMM_SMEM_BYTES>>>(pxt, pwqkv, pq, pk, pv, Cq, Cq, 1, nullptr);

    // 3-5) fused scores + softmax + ctx
    dim3 gattn(Tq / 128, BHq);
    attn_fused<<<gattn, 256, attn_smem>>>(wei);

    // 6) out = ctx @ Wproj^T + b  via 2-term tf32 split (K=2048)
    conv_ctx2_kernel<<<(Mq * Cq) / 256, 256>>>(pctx, pctx2);
    dim3 gout(Cq / 128, Mq / 128, 1);
    gemm_mma2<<<gout, 256, GEMM_SMEM_BYTES>>>(pctx2, pwp2, out, nullptr, nullptr,
                                              2 * Cq, Cq, 0, bproj);
}

// round 7
// speedup vs baseline: 2.5402x; 1.0326x over previous
#include <cuda_runtime.h>
#include <math.h>
#include <stdint.h>

// Problem constants
#define Bq 8
#define Tq 1024
#define Cq 1024
#define Hq 16
#define Dq 64
#define Mq (Bq * Tq)          // 8192 rows
#define BHq (Bq * Hq)         // 128

// ---------------------------------------------------------------------------
// Scratch (device globals; no dynamic allocation allowed)
// ---------------------------------------------------------------------------
__device__ float g_q[(size_t)BHq * Tq * Dq];      // [B,H,T,D]  32 MB
__device__ float g_k[(size_t)BHq * Tq * Dq];      // 32 MB
__device__ float g_v[(size_t)BHq * Tq * Dq];      // 32 MB
__device__ float g_ctx[(size_t)Mq * Cq];          // [B,T,C]    32 MB
__device__ float g_xt[(size_t)Mq * Cq];           // x, tf32-rounded   32 MB
__device__ float g_wqkv[(size_t)3 * Cq * Cq];     // packed [3][N=HD][K=C] tf32
__device__ float g_ctx2[(size_t)Mq * 2 * Cq];     // split ctx [M, 2C]  64 MB
__device__ float g_wp2[(size_t)Cq * 2 * Cq];      // Wproj tf32 [N, 2C]  8 MB
__device__ float g_invl[(size_t)BHq * Tq];        // 1/rowsum per (bh,t)

__device__ __forceinline__ float f2tf32(float a) {
    uint32_t r;
    asm("cvt.rna.tf32.f32 %0, %1;" : "=r"(r) : "f"(a));
    return __uint_as_float(r);
}
__device__ __forceinline__ uint32_t smem_u32(const void* p) {
    uint32_t a;
    asm("{ .reg .u64 t; cvta.to.shared.u64 t, %1; cvt.u32.u64 %0, t; }" : "=r"(a) : "l"(p));
    return a;
}

// ---------------------------------------------------------------------------
// Conversion / repack kernels
// ---------------------------------------------------------------------------
__global__ void conv_x4_kernel(const float4* __restrict__ x, float4* __restrict__ xt) {
    int i = blockIdx.x * blockDim.x + threadIdx.x;
    float4 v = x[i];
    v.x = f2tf32(v.x); v.y = f2tf32(v.y); v.z = f2tf32(v.z); v.w = f2tf32(v.w);
    xt[i] = v;
}

// Wq/Wk/Wv [H,C,D] -> packed [3][N=HD][K=C], tf32; blockIdx.y selects matrix
__global__ void conv_wqkv3_kernel(const float* __restrict__ Wq,
                                  const float* __restrict__ Wk,
                                  const float* __restrict__ Wv,
                                  float* __restrict__ P) {
    int i = blockIdx.x * blockDim.x + threadIdx.x;
    int z = blockIdx.y;
    const float* W = (z == 0) ? Wq : (z == 1) ? Wk : Wv;
    int n = i >> 10;
    int c = i & 1023;
    int h = n >> 6, d = n & 63;
    P[(size_t)z * Cq * Cq + (size_t)n * Cq + c] = f2tf32(W[((size_t)h * Cq + c) * Dq + d]);
}

// Wproj [N,K] -> [N, 2K]: (hi | hi)
__global__ void conv_wp2_kernel(const float* __restrict__ W, float* __restrict__ P) {
    int i = blockIdx.x * blockDim.x + threadIdx.x;
    int n = i >> 10;
    int c = i & 1023;
    float hi = f2tf32(W[(size_t)n * Cq + c]);
    size_t base = (size_t)n * (2 * Cq);
    P[base + c]      = hi;
    P[base + Cq + c] = hi;
}

// ctx [M,C] -> [M, 2C]: (hi | lo)
__global__ void conv_ctx2_kernel(const float* __restrict__ S, float* __restrict__ P) {
    int i = blockIdx.x * blockDim.x + threadIdx.x;
    int m = i >> 10;
    int c = i & 1023;
    float a  = S[(size_t)m * Cq + c];
    float hi = f2tf32(a);
    float lo = f2tf32(a - hi);
    size_t base = (size_t)m * (2 * Cq);
    P[base + c]      = hi;
    P[base + Cq + c] = lo;
}

// ---------------------------------------------------------------------------
// mma helper
// ---------------------------------------------------------------------------
__device__ __forceinline__ void mma_tf32(float c[4], uint32_t a0, uint32_t a1,
                                         uint32_t a2, uint32_t a3,
                                         uint32_t b0, uint32_t b1) {
    asm volatile(
        "mma.sync.aligned.m16n8k8.row.col.f32.tf32.tf32.f32 "
        "{%0,%1,%2,%3}, {%4,%5,%6,%7}, {%8,%9}, {%0,%1,%2,%3};"
        : "+f"(c[0]), "+f"(c[1]), "+f"(c[2]), "+f"(c[3])
        : "r"(a0), "r"(a1), "r"(a2), "r"(a3), "r"(b0), "r"(b1));
}

// ---------------------------------------------------------------------------
// cp.async double-buffered warp-MMA tf32 GEMM (unchanged from R5).
// ---------------------------------------------------------------------------
#define GST 36
#define STGF (2 * 128 * GST)
#define GEMM_SMEM_BYTES (2 * STGF * 4)

__global__ __launch_bounds__(256) void gemm_mma2(
    const float* __restrict__ A, const float* __restrict__ BwBase,
    float* __restrict__ O0, float* __restrict__ O1, float* __restrict__ O2,
    int K, int Nout, int mode, const float* __restrict__ bias)
{
    extern __shared__ float smem[];
    const float* Bw = BwBase + ((mode == 1) ? (size_t)blockIdx.z * Cq * Cq : 0);
    float* Cout = (mode == 1) ? (blockIdx.z == 0 ? O0 : blockIdx.z == 1 ? O1 : O2) : O0;

    const int tid  = threadIdx.x;
    const int wid  = tid >> 5;
    const int lane = tid & 31;
    const int row0 = blockIdx.y * 128;
    const int col0 = blockIdx.x * 128;
    const int wm   = (wid & 3) * 32;
    const int wn   = (wid >> 2) * 64;
    const uint32_t smb = smem_u32(smem);

    int lrow[4], lc4[4];
#pragma unroll
    for (int l = 0; l < 4; l++) {
        int idx = l * 256 + tid;
        lrow[l] = idx >> 3;
        lc4[l]  = (idx & 7) << 2;
    }

    const int NC = K >> 5;

#define ISSUE_STAGE(s)                                                          \
    do {                                                                        \
        const int k0 = (s) << 5;                                                \
        const uint32_t sb = smb + ((s) & 1) * (STGF * 4);                       \
        _Pragma("unroll")                                                       \
        for (int l = 0; l < 4; l++) {                                           \
            uint32_t da = sb + (uint32_t)(lrow[l] * GST + lc4[l]) * 4;          \
            const float* sa = A + (size_t)(row0 + lrow[l]) * K + k0 + lc4[l];   \
            asm volatile("cp.async.cg.shared.global [%0], [%1], 16;"            \
                         :: "r"(da), "l"(sa));                                  \
            uint32_t db = sb + (uint32_t)(128 * GST + lrow[l] * GST + lc4[l]) * 4; \
            const float* sbp = Bw + (size_t)(col0 + lrow[l]) * K + k0 + lc4[l]; \
            asm volatile("cp.async.cg.shared.global [%0], [%1], 16;"            \
                         :: "r"(db), "l"(sbp));                                 \
        }                                                                       \
        asm volatile("cp.async.commit_group;");                                 \
    } while (0)

    float acc[2][8][4];
#pragma unroll
    for (int mt = 0; mt < 2; mt++)
#pragma unroll
        for (int nt = 0; nt < 8; nt++)
#pragma unroll
            for (int j = 0; j < 4; j++) acc[mt][nt][j] = 0.f;

    ISSUE_STAGE(0);
    if (1 < NC) ISSUE_STAGE(1); else asm volatile("cp.async.commit_group;");

    for (int i = 0; i < NC; i++) {
        asm volatile("cp.async.wait_group 1;");
        __syncthreads();

        const float* As_ = smem + (i & 1) * STGF;
        const float* Bs_ = As_ + 128 * GST;

#pragma unroll
        for (int ks = 0; ks < 4; ks++) {
            const int kb = ks * 8;
            const int arow = wm + (lane >> 2);
            const int acol = kb + (lane & 3);
            uint32_t af[2][4];
#pragma unroll
            for (int mt = 0; mt < 2; mt++) {
                af[mt][0] = __float_as_uint(As_[(arow + mt * 16    ) * GST + acol    ]);
                af[mt][1] = __float_as_uint(As_[(arow + mt * 16 + 8) * GST + acol    ]);
                af[mt][2] = __float_as_uint(As_[(arow + mt * 16    ) * GST + acol + 4]);
                af[mt][3] = __float_as_uint(As_[(arow + mt * 16 + 8) * GST + acol + 4]);
            }
            const int brow = wn + (lane >> 2);
            const int bcol = kb + (lane & 3);
            uint32_t bf[8][2];
#pragma unroll
            for (int nt = 0; nt < 8; nt++) {
                bf[nt][0] = __float_as_uint(Bs_[(brow + nt * 8) * GST + bcol    ]);
                bf[nt][1] = __float_as_uint(Bs_[(brow + nt * 8) * GST + bcol + 4]);
            }
#pragma unroll
            for (int mt = 0; mt < 2; mt++)
#pragma unroll
                for (int nt = 0; nt < 8; nt++)
                    mma_tf32(acc[mt][nt], af[mt][0], af[mt][1], af[mt][2], af[mt][3],
                             bf[nt][0], bf[nt][1]);
        }
        __syncthreads();

        if (i + 2 < NC) ISSUE_STAGE(i + 2);
        else asm volatile("cp.async.commit_group;");
    }

    const int er = lane >> 2;
    const int ec = (lane & 3) << 1;
#pragma unroll
    for (int mt = 0; mt < 2; mt++) {
#pragma unroll
        for (int nt = 0; nt < 8; nt++) {
#pragma unroll
            for (int half = 0; half < 2; half++) {
                int m = row0 + wm + mt * 16 + er + half * 8;
#pragma unroll
                for (int j = 0; j < 2; j++) {
                    int n = col0 + wn + nt * 8 + ec + j;
                    float v = acc[mt][nt][half * 2 + j];
                    if (mode == 0) {
                        if (bias) v += bias[n];
                        Cout[(size_t)m * Nout + n] = v;
                    } else {
                        int b = m >> 10, t = m & 1023;
                        int h = n >> 6, d = n & 63;
                        Cout[((size_t)(b * Hq + h) << 16) + ((size_t)t << 6) + d] = v;
                    }
                }
            }
        }
    }
#undef ISSUE_STAGE
}

// ---------------------------------------------------------------------------
// Fused attention, ONE pass, no-max softmax (scores bounded; diagonal => l>=1).
// Writes UNNORMALIZED E=exp(S) to wei (rescaled by rescale_wei afterwards),
// accumulates ctx = (E·V) / l, stores 1/l to g_invl.
// Grid: (Tq/128, BHq), 256 threads = 8 warps, warp w owns rows w*16..w*16+15.
// ---------------------------------------------------------------------------
#define AST 72
#define ATTN_SMEM_FLOATS (128 * AST + 64 * AST + 64 * AST + 128 * AST)

__global__ __launch_bounds__(256, 1) void attn_fused(float* __restrict__ wei) {
    extern __shared__ float sm[];
    float* Qs = sm;
    float* Ks = Qs + 128 * AST;
    float* Vs = Ks + 64 * AST;
    float* Ps = Vs + 64 * AST;

    const int tid  = threadIdx.x;
    const int wid  = tid >> 5;
    const int lane = tid & 31;
    const int tB   = blockIdx.x;
    const int bh   = blockIdx.y;
    const int wm   = wid * 16;
    const int trow0 = tB * 128 + wm + (lane >> 2);
    const int trow1 = trow0 + 8;

    const float* qb = g_q + (size_t)bh * Tq * Dq + (size_t)tB * 128 * Dq;
    const float* kb = g_k + (size_t)bh * Tq * Dq;
    const float* vb = g_v + (size_t)bh * Tq * Dq;
    float* wb = wei + (size_t)bh * Tq * Tq + (size_t)tB * 128 * Tq;

    // load Q tile (tf32-rounded, once)
#pragma unroll
    for (int l = 0; l < 8; l++) {
        int f = tid + l * 256;
        int r = f >> 4, c4 = (f & 15) << 2;
        float4 v = *(const float4*)(qb + (size_t)r * Dq + c4);
        Qs[r * AST + c4 + 0] = f2tf32(v.x);
        Qs[r * AST + c4 + 1] = f2tf32(v.y);
        Qs[r * AST + c4 + 2] = f2tf32(v.z);
        Qs[r * AST + c4 + 3] = f2tf32(v.w);
    }
    __syncthreads();

    // persistent Q fragments
    uint32_t af[8][4];
    {
        const int arow = wm + (lane >> 2);
#pragma unroll
        for (int ks = 0; ks < 8; ks++) {
            const int acol = ks * 8 + (lane & 3);
            af[ks][0] = __float_as_uint(Qs[(arow    ) * AST + acol    ]);
            af[ks][1] = __float_as_uint(Qs[(arow + 8) * AST + acol    ]);
            af[ks][2] = __float_as_uint(Qs[(arow    ) * AST + acol + 4]);
            af[ks][3] = __float_as_uint(Qs[(arow + 8) * AST + acol + 4]);
        }
    }

    const int nS = 2 * tB + 2;
    float l0 = 0.f, l1 = 0.f;           // per-lane partial row sums
    float ctx[8][4];
#pragma unroll
    for (int nt = 0; nt < 8; nt++)
        { ctx[nt][0]=0.f; ctx[nt][1]=0.f; ctx[nt][2]=0.f; ctx[nt][3]=0.f; }

    for (int sT = 0; sT < nS; sT++) {
        // load K (tf32) + V (raw; HW truncation in mma)
#pragma unroll
        for (int l = 0; l < 4; l++) {
            int f = tid + l * 256;
            int r = f >> 4, c4 = (f & 15) << 2;
            float4 v = *(const float4*)(kb + (size_t)(sT * 64 + r) * Dq + c4);
            Ks[r * AST + c4 + 0] = f2tf32(v.x);
            Ks[r * AST + c4 + 1] = f2tf32(v.y);
            Ks[r * AST + c4 + 2] = f2tf32(v.z);
            Ks[r * AST + c4 + 3] = f2tf32(v.w);
            *(float4*)(Vs + r * AST + c4) = *(const float4*)(vb + (size_t)(sT * 64 + r) * Dq + c4);
        }
        __syncthreads();

        // S = Q·K^T / 8, causal mask on diagonal band
        float sacc[8][4];
#pragma unroll
        for (int nt = 0; nt < 8; nt++)
            { sacc[nt][0]=0.f; sacc[nt][1]=0.f; sacc[nt][2]=0.f; sacc[nt][3]=0.f; }
#pragma unroll
        for (int ks = 0; ks < 8; ks++) {
            uint32_t bf[8][2];
#pragma unroll
            for (int nt = 0; nt < 8; nt++) {
                int srow = nt * 8 + (lane >> 2);
                int scol = ks * 8 + (lane & 3);
                bf[nt][0] = __float_as_uint(Ks[srow * AST + scol]);
                bf[nt][1] = __float_as_uint(Ks[srow * AST + scol + 4]);
            }
#pragma unroll
            for (int nt = 0; nt < 8; nt++)
                mma_tf32(sacc[nt], af[ks][0], af[ks][1], af[ks][2], af[ks][3],
                         bf[nt][0], bf[nt][1]);
        }

        const bool mask = (sT >= 2 * tB);
        // E = exp(S/8) (no max needed: scores bounded, diagonal => l >= 1)
        {
            const int pr = wm + (lane >> 2);
            const int pc = (lane & 3) << 1;
#pragma unroll
            for (int nt = 0; nt < 8; nt++) {
                float s0v = sacc[nt][0] * 0.125f;
                float s1v = sacc[nt][1] * 0.125f;
                float s2v = sacc[nt][2] * 0.125f;
                float s3v = sacc[nt][3] * 0.125f;
                if (mask) {
                    int s0 = sT * 64 + nt * 8 + ((lane & 3) << 1);
                    if (s0     > trow0) s0v = -INFINITY;
                    if (s0 + 1 > trow0) s1v = -INFINITY;
                    if (s0     > trow1) s2v = -INFINITY;
                    if (s0 + 1 > trow1) s3v = -INFINITY;
                }
                float e0 = __expf(s0v), e1 = __expf(s1v);
                float e2 = __expf(s2v), e3 = __expf(s3v);
                l0 += e0 + e1;
                l1 += e2 + e3;
                Ps[(pr    ) * AST + nt * 8 + pc    ] = e0;
                Ps[(pr    ) * AST + nt * 8 + pc + 1] = e1;
                Ps[(pr + 8) * AST + nt * 8 + pc    ] = e2;
                Ps[(pr + 8) * AST + nt * 8 + pc + 1] = e3;
            }
        }
        __syncthreads();

        // write unnormalized E tile to wei (coalesced float4)
#pragma unroll
        for (int l = 0; l < 8; l++) {
            int f = tid + l * 256;
            int r = f >> 4, c4 = (f & 15) << 2;
            *(float4*)(wb + (size_t)r * Tq + sT * 64 + c4) = *(const float4*)(Ps + r * AST + c4);
        }

        // ctx += E·V (raw bits; HW tf32 truncation)
#pragma unroll
        for (int ks = 0; ks < 8; ks++) {
            const int arow = wm + (lane >> 2);
            const int acol = ks * 8 + (lane & 3);
            uint32_t ap[4];
            ap[0] = __float_as_uint(Ps[(arow    ) * AST + acol    ]);
            ap[1] = __float_as_uint(Ps[(arow + 8) * AST + acol    ]);
            ap[2] = __float_as_uint(Ps[(arow    ) * AST + acol + 4]);
            ap[3] = __float_as_uint(Ps[(arow + 8) * AST + acol + 4]);
            uint32_t bv[8][2];
#pragma unroll
            for (int nt = 0; nt < 8; nt++) {
                int vrow = ks * 8 + (lane & 3);
                int vcol = nt * 8 + (lane >> 2);
                bv[nt][0] = __float_as_uint(Vs[(vrow    ) * AST + vcol]);
                bv[nt][1] = __float_as_uint(Vs[(vrow + 4) * AST + vcol]);
            }
#pragma unroll
            for (int nt = 0; nt < 8; nt++)
                mma_tf32(ctx[nt], ap[0], ap[1], ap[2], ap[3], bv[nt][0], bv[nt][1]);
        }
        __syncthreads();
    }

    // reduce row sums across quad lanes (once, not per tile)
    l0 += __shfl_xor_sync(0xffffffffu, l0, 1);
    l0 += __shfl_xor_sync(0xffffffffu, l0, 2);
    l1 += __shfl_xor_sync(0xffffffffu, l1, 1);
    l1 += __shfl_xor_sync(0xffffffffu, l1, 2);
    const float inv0 = 1.0f / l0;
    const float inv1 = 1.0f / l1;

    if ((lane & 3) == 0) {
        g_invl[(size_t)bh * Tq + trow0] = inv0;
        g_invl[(size_t)bh * Tq + trow1] = inv1;
    }

    // zero-fill upper triangle region (cols >= nS*64)
    {
        const int nz4 = (16 - nS) * 16;
        if (nz4 > 0) {
            const float4 z = {0.f, 0.f, 0.f, 0.f};
            for (int f = tid; f < 128 * nz4; f += 256) {
                int r  = f / nz4;
                int c4 = (f - r * nz4) << 2;
                *(float4*)(wb + (size_t)r * Tq + nS * 64 + c4) = z;
            }
        }
    }

    // write normalized ctx -> g_ctx [B,T,C]
    {
        const int b = bh >> 4, h = bh & 15;
        const int ec = (lane & 3) << 1;
#pragma unroll
        for (int nt = 0; nt < 8; nt++) {
            float2 v0 = {ctx[nt][0] * inv0, ctx[nt][1] * inv0};
            float2 v1 = {ctx[nt][2] * inv1, ctx[nt][3] * inv1};
            int c = h * 64 + nt * 8 + ec;
            *(float2*)(g_ctx + ((size_t)(b * Tq + trow0) << 10) + c) = v0;
            *(float2*)(g_ctx + ((size_t)(b * Tq + trow1) << 10) + c) = v1;
        }
    }
}

// ---------------------------------------------------------------------------
// Rescale wei rows by 1/l. Causal region only (zeros beyond stay zero).
// Grid (Tq/2, BHq), 256 threads: 2 rows/block, 128 threads/row.
// Row t written region = ((t>>7)+1)*128 floats = ((t>>7)+1)*32 float4.
// ---------------------------------------------------------------------------
__global__ __launch_bounds__(256) void rescale_wei(float* __restrict__ wei) {
    const int bh = blockIdx.y;
    const int t  = blockIdx.x * 2 + (threadIdx.x >> 7);
    const int ln = threadIdx.x & 127;
    const float inv = g_invl[(size_t)bh * Tq + t];
    float4* row = (float4*)(wei + (size_t)bh * Tq * Tq + (size_t)t * Tq);
    const int n4 = ((t >> 7) + 1) * 32;
#pragma unroll 2
    for (int w = ln; w < n4; w += 128) {
        float4 v = row[w];
        v.x *= inv; v.y *= inv; v.z *= inv; v.w *= inv;
        row[w] = v;
    }
}

// ---------------------------------------------------------------------------
// Launch
// ---------------------------------------------------------------------------
extern "C" void kernel_launch(void* const* d_in, const int* in_sizes, int n_in,
                              void* d_out, int out_size) {
    const float* x     = (const float*)d_in[0];
    const float* Wq    = (const float*)d_in[1];
    const float* Wk    = (const float*)d_in[2];
    const float* Wv    = (const float*)d_in[3];
    const float* Wproj = (const float*)d_in[4];
    const float* bproj = (const float*)d_in[5];

    float* out = (float*)d_out;                       // [B,T,C]
    float* wei = out + (size_t)Bq * Tq * Cq;          // [B,H,T,T]

    float *pq, *pk, *pv, *pctx, *pxt, *pwqkv, *pctx2, *pwp2;
    cudaGetSymbolAddress((void**)&pq,    g_q);
    cudaGetSymbolAddress((void**)&pk,    g_k);
    cudaGetSymbolAddress((void**)&pv,    g_v);
    cudaGetSymbolAddress((void**)&pctx,  g_ctx);
    cudaGetSymbolAddress((void**)&pxt,   g_xt);
    cudaGetSymbolAddress((void**)&pwqkv, g_wqkv);
    cudaGetSymbolAddress((void**)&pctx2, g_ctx2);
    cudaGetSymbolAddress((void**)&pwp2,  g_wp2);

    const int attn_smem = ATTN_SMEM_FLOATS * 4;
    cudaFuncSetAttribute(attn_fused, cudaFuncAttributeMaxDynamicSharedMemorySize, attn_smem);
    cudaFuncSetAttribute(gemm_mma2, cudaFuncAttributeMaxDynamicSharedMemorySize, GEMM_SMEM_BYTES);

    // 1) tf32 rounding / repacking of GEMM inputs
    conv_x4_kernel<<<(Mq * Cq / 4) / 256, 256>>>((const float4*)x, (float4*)pxt);
    dim3 gw((Cq * Cq) / 256, 3);
    conv_wqkv3_kernel<<<gw, 256>>>(Wq, Wk, Wv, pwqkv);
    conv_wp2_kernel<<<(Cq * Cq) / 256, 256>>>(Wproj, pwp2);

    // 2) Q/K/V projections: one z=3 grid on tensor cores
    dim3 gqkv(Cq / 128, Mq / 128, 3);
    gemm_mma2<<<gqkv, 256, GEMM_SMEM_BYTES>>>(pxt, pwqkv, pq, pk, pv, Cq, Cq, 1, nullptr);

    // 3) fused one-pass attention (wei unnormalized) + ctx
    dim3 gattn(Tq / 128, BHq);
    attn_fused<<<gattn, 256, attn_smem>>>(wei);

    // 4) normalize wei rows
    dim3 grs(Tq / 2, BHq);
    rescale_wei<<<grs, 256>>>(wei);

    // 5) out = ctx @ Wproj^T + b  via 2-term tf32 split (K=2048)
    conv_ctx2_kernel<<<(Mq * Cq) / 256, 256>>>(pctx, pctx2);
    dim3 gout(Cq / 128, Mq / 128, 1);
    gemm_mma2<<<gout, 256, GEMM_SMEM_BYTES>>>(pctx2, pwp2, out, nullptr, nullptr,
                                              2 * Cq, Cq, 0, bproj);
}

// round 8
// speedup vs baseline: 2.7125x; 1.0678x over previous
#include <cuda_runtime.h>
#include <math.h>
#include <stdint.h>

// Problem constants
#define Bq 8
#define Tq 1024
#define Cq 1024
#define Hq 16
#define Dq 64
#define Mq (Bq * Tq)          // 8192 rows
#define BHq (Bq * Hq)         // 128

// ---------------------------------------------------------------------------
// Scratch (device globals; no dynamic allocation allowed)
// ---------------------------------------------------------------------------
__device__ float g_q[(size_t)BHq * Tq * Dq];      // [B,H,T,D]  32 MB
__device__ float g_k[(size_t)BHq * Tq * Dq];      // 32 MB
__device__ float g_v[(size_t)BHq * Tq * Dq];      // 32 MB
__device__ float g_xt[(size_t)Mq * Cq];           // x, tf32-rounded   32 MB
__device__ float g_wqkv[(size_t)3 * Cq * Cq];     // packed [3][N=HD][K=C] tf32
__device__ float g_ctx2[(size_t)Mq * 2 * Cq];     // split ctx [M, 2C] (hi|lo)  64 MB
__device__ float g_wp2[(size_t)Cq * 2 * Cq];      // Wproj tf32 [N, 2C]  8 MB
__device__ float g_invl[(size_t)BHq * Tq];        // 1/rowsum per (bh,t)

__device__ __forceinline__ float f2tf32(float a) {
    uint32_t r;
    asm("cvt.rna.tf32.f32 %0, %1;" : "=r"(r) : "f"(a));
    return __uint_as_float(r);
}
__device__ __forceinline__ uint32_t smem_u32(const void* p) {
    uint32_t a;
    asm("{ .reg .u64 t; cvta.to.shared.u64 t, %1; cvt.u32.u64 %0, t; }" : "=r"(a) : "l"(p));
    return a;
}

// ---------------------------------------------------------------------------
// Conversion / repack kernels
// ---------------------------------------------------------------------------
__global__ void conv_x4_kernel(const float4* __restrict__ x, float4* __restrict__ xt) {
    int i = blockIdx.x * blockDim.x + threadIdx.x;
    float4 v = x[i];
    v.x = f2tf32(v.x); v.y = f2tf32(v.y); v.z = f2tf32(v.z); v.w = f2tf32(v.w);
    xt[i] = v;
}

// Wq/Wk/Wv [H,C,D] -> packed [3][N=HD][K=C], tf32; blockIdx.y selects matrix
__global__ void conv_wqkv3_kernel(const float* __restrict__ Wq,
                                  const float* __restrict__ Wk,
                                  const float* __restrict__ Wv,
                                  float* __restrict__ P) {
    int i = blockIdx.x * blockDim.x + threadIdx.x;
    int z = blockIdx.y;
    const float* W = (z == 0) ? Wq : (z == 1) ? Wk : Wv;
    int n = i >> 10;
    int c = i & 1023;
    int h = n >> 6, d = n & 63;
    P[(size_t)z * Cq * Cq + (size_t)n * Cq + c] = f2tf32(W[((size_t)h * Cq + c) * Dq + d]);
}

// Wproj [N,K] -> [N, 2K]: (hi | hi)
__global__ void conv_wp2_kernel(const float* __restrict__ W, float* __restrict__ P) {
    int i = blockIdx.x * blockDim.x + threadIdx.x;
    int n = i >> 10;
    int c = i & 1023;
    float hi = f2tf32(W[(size_t)n * Cq + c]);
    size_t base = (size_t)n * (2 * Cq);
    P[base + c]      = hi;
    P[base + Cq + c] = hi;
}

// ---------------------------------------------------------------------------
// mma helper
// ---------------------------------------------------------------------------
__device__ __forceinline__ void mma_tf32(float c[4], uint32_t a0, uint32_t a1,
                                         uint32_t a2, uint32_t a3,
                                         uint32_t b0, uint32_t b1) {
    asm volatile(
        "mma.sync.aligned.m16n8k8.row.col.f32.tf32.tf32.f32 "
        "{%0,%1,%2,%3}, {%4,%5,%6,%7}, {%8,%9}, {%0,%1,%2,%3};"
        : "+f"(c[0]), "+f"(c[1]), "+f"(c[2]), "+f"(c[3])
        : "r"(a0), "r"(a1), "r"(a2), "r"(a3), "r"(b0), "r"(b1));
}

// ---------------------------------------------------------------------------
// cp.async double-buffered warp-MMA tf32 GEMM (as R5/R6).
// ---------------------------------------------------------------------------
#define GST 36
#define STGF (2 * 128 * GST)
#define GEMM_SMEM_BYTES (2 * STGF * 4)

__global__ __launch_bounds__(256) void gemm_mma2(
    const float* __restrict__ A, const float* __restrict__ BwBase,
    float* __restrict__ O0, float* __restrict__ O1, float* __restrict__ O2,
    int K, int Nout, int mode, const float* __restrict__ bias)
{
    extern __shared__ float smem[];
    const float* Bw = BwBase + ((mode == 1) ? (size_t)blockIdx.z * Cq * Cq : 0);
    float* Cout = (mode == 1) ? (blockIdx.z == 0 ? O0 : blockIdx.z == 1 ? O1 : O2) : O0;

    const int tid  = threadIdx.x;
    const int wid  = tid >> 5;
    const int lane = tid & 31;
    const int row0 = blockIdx.y * 128;
    const int col0 = blockIdx.x * 128;
    const int wm   = (wid & 3) * 32;
    const int wn   = (wid >> 2) * 64;
    const uint32_t smb = smem_u32(smem);

    int lrow[4], lc4[4];
#pragma unroll
    for (int l = 0; l < 4; l++) {
        int idx = l * 256 + tid;
        lrow[l] = idx >> 3;
        lc4[l]  = (idx & 7) << 2;
    }

    const int NC = K >> 5;

#define ISSUE_STAGE(s)                                                          \
    do {                                                                        \
        const int k0 = (s) << 5;                                                \
        const uint32_t sb = smb + ((s) & 1) * (STGF * 4);                       \
        _Pragma("unroll")                                                       \
        for (int l = 0; l < 4; l++) {                                           \
            uint32_t da = sb + (uint32_t)(lrow[l] * GST + lc4[l]) * 4;          \
            const float* sa = A + (size_t)(row0 + lrow[l]) * K + k0 + lc4[l];   \
            asm volatile("cp.async.cg.shared.global [%0], [%1], 16;"            \
                         :: "r"(da), "l"(sa));                                  \
            uint32_t db = sb + (uint32_t)(128 * GST + lrow[l] * GST + lc4[l]) * 4; \
            const float* sbp = Bw + (size_t)(col0 + lrow[l]) * K + k0 + lc4[l]; \
            asm volatile("cp.async.cg.shared.global [%0], [%1], 16;"            \
                         :: "r"(db), "l"(sbp));                                 \
        }                                                                       \
        asm volatile("cp.async.commit_group;");                                 \
    } while (0)

    float acc[2][8][4];
#pragma unroll
    for (int mt = 0; mt < 2; mt++)
#pragma unroll
        for (int nt = 0; nt < 8; nt++)
#pragma unroll
            for (int j = 0; j < 4; j++) acc[mt][nt][j] = 0.f;

    ISSUE_STAGE(0);
    if (1 < NC) ISSUE_STAGE(1); else asm volatile("cp.async.commit_group;");

    for (int i = 0; i < NC; i++) {
        asm volatile("cp.async.wait_group 1;");
        __syncthreads();

        const float* As_ = smem + (i & 1) * STGF;
        const float* Bs_ = As_ + 128 * GST;

#pragma unroll
        for (int ks = 0; ks < 4; ks++) {
            const int kb = ks * 8;
            const int arow = wm + (lane >> 2);
            const int acol = kb + (lane & 3);
            uint32_t af[2][4];
#pragma unroll
            for (int mt = 0; mt < 2; mt++) {
                af[mt][0] = __float_as_uint(As_[(arow + mt * 16    ) * GST + acol    ]);
                af[mt][1] = __float_as_uint(As_[(arow + mt * 16 + 8) * GST + acol    ]);
                af[mt][2] = __float_as_uint(As_[(arow + mt * 16    ) * GST + acol + 4]);
                af[mt][3] = __float_as_uint(As_[(arow + mt * 16 + 8) * GST + acol + 4]);
            }
            const int brow = wn + (lane >> 2);
            const int bcol = kb + (lane & 3);
            uint32_t bf[8][2];
#pragma unroll
            for (int nt = 0; nt < 8; nt++) {
                bf[nt][0] = __float_as_uint(Bs_[(brow + nt * 8) * GST + bcol    ]);
                bf[nt][1] = __float_as_uint(Bs_[(brow + nt * 8) * GST + bcol + 4]);
            }
#pragma unroll
            for (int mt = 0; mt < 2; mt++)
#pragma unroll
                for (int nt = 0; nt < 8; nt++)
                    mma_tf32(acc[mt][nt], af[mt][0], af[mt][1], af[mt][2], af[mt][3],
                             bf[nt][0], bf[nt][1]);
        }
        __syncthreads();

        if (i + 2 < NC) ISSUE_STAGE(i + 2);
        else asm volatile("cp.async.commit_group;");
    }

    const int er = lane >> 2;
    const int ec = (lane & 3) << 1;
#pragma unroll
    for (int mt = 0; mt < 2; mt++) {
#pragma unroll
        for (int nt = 0; nt < 8; nt++) {
#pragma unroll
            for (int half = 0; half < 2; half++) {
                int m = row0 + wm + mt * 16 + er + half * 8;
#pragma unroll
                for (int j = 0; j < 2; j++) {
                    int n = col0 + wn + nt * 8 + ec + j;
                    float v = acc[mt][nt][half * 2 + j];
                    if (mode == 0) {
                        if (bias) v += bias[n];
                        Cout[(size_t)m * Nout + n] = v;
                    } else {
                        int b = m >> 10, t = m & 1023;
                        int h = n >> 6, d = n & 63;
                        Cout[((size_t)(b * Hq + h) << 16) + ((size_t)t << 6) + d] = v;
                    }
                }
            }
        }
    }
#undef ISSUE_STAGE
}

// ---------------------------------------------------------------------------
// Fused attention, one pass, no-max softmax (scores bounded; diagonal => l>=1).
// Writes UNNORMALIZED E=exp(S) to wei; ctx = (E·V)/l written in split (hi|lo)
// form directly to g_ctx2; 1/l stored to g_invl.
// K/V tiles register-prefetched across the s-loop.
// ---------------------------------------------------------------------------
#define AST 72
#define ATTN_SMEM_FLOATS (128 * AST + 64 * AST + 64 * AST + 128 * AST)

__global__ __launch_bounds__(256, 1) void attn_fused(float* __restrict__ wei) {
    extern __shared__ float sm[];
    float* Qs = sm;
    float* Ks = Qs + 128 * AST;
    float* Vs = Ks + 64 * AST;
    float* Ps = Vs + 64 * AST;

    const int tid  = threadIdx.x;
    const int wid  = tid >> 5;
    const int lane = tid & 31;
    const int tB   = blockIdx.x;
    const int bh   = blockIdx.y;
    const int wm   = wid * 16;
    const int trow0 = tB * 128 + wm + (lane >> 2);
    const int trow1 = trow0 + 8;

    const float* qb = g_q + (size_t)bh * Tq * Dq + (size_t)tB * 128 * Dq;
    const float* kb = g_k + (size_t)bh * Tq * Dq;
    const float* vb = g_v + (size_t)bh * Tq * Dq;
    float* wb = wei + (size_t)bh * Tq * Tq + (size_t)tB * 128 * Tq;

    // per-thread K/V load geometry (4 float4 each)
    const int lr = tid >> 4;               // row 0..15 (+16 per l)
    const int lc = (tid & 15) << 2;        // col 0..60

    // load Q tile (tf32-rounded, once)
#pragma unroll
    for (int l = 0; l < 8; l++) {
        int f = tid + l * 256;
        int r = f >> 4, c4 = (f & 15) << 2;
        float4 v = *(const float4*)(qb + (size_t)r * Dq + c4);
        Qs[r * AST + c4 + 0] = f2tf32(v.x);
        Qs[r * AST + c4 + 1] = f2tf32(v.y);
        Qs[r * AST + c4 + 2] = f2tf32(v.z);
        Qs[r * AST + c4 + 3] = f2tf32(v.w);
    }
    __syncthreads();

    // persistent Q fragments
    uint32_t af[8][4];
    {
        const int arow = wm + (lane >> 2);
#pragma unroll
        for (int ks = 0; ks < 8; ks++) {
            const int acol = ks * 8 + (lane & 3);
            af[ks][0] = __float_as_uint(Qs[(arow    ) * AST + acol    ]);
            af[ks][1] = __float_as_uint(Qs[(arow + 8) * AST + acol    ]);
            af[ks][2] = __float_as_uint(Qs[(arow    ) * AST + acol + 4]);
            af[ks][3] = __float_as_uint(Qs[(arow + 8) * AST + acol + 4]);
        }
    }

    const int nS = 2 * tB + 2;
    float l0 = 0.f, l1 = 0.f;
    float ctx[8][4];
#pragma unroll
    for (int nt = 0; nt < 8; nt++)
        { ctx[nt][0]=0.f; ctx[nt][1]=0.f; ctx[nt][2]=0.f; ctx[nt][3]=0.f; }

    // prologue: load tile 0 K/V into registers
    float4 pk[4], pv[4];
#pragma unroll
    for (int l = 0; l < 4; l++) {
        int r = lr + l * 16;
        pk[l] = *(const float4*)(kb + (size_t)r * Dq + lc);
        pv[l] = *(const float4*)(vb + (size_t)r * Dq + lc);
    }

    for (int sT = 0; sT < nS; sT++) {
        // store current K (tf32-rounded) and V (tf32-rounded) to smem
#pragma unroll
        for (int l = 0; l < 4; l++) {
            int r = lr + l * 16;
            Ks[r * AST + lc + 0] = f2tf32(pk[l].x);
            Ks[r * AST + lc + 1] = f2tf32(pk[l].y);
            Ks[r * AST + lc + 2] = f2tf32(pk[l].z);
            Ks[r * AST + lc + 3] = f2tf32(pk[l].w);
            Vs[r * AST + lc + 0] = f2tf32(pv[l].x);
            Vs[r * AST + lc + 1] = f2tf32(pv[l].y);
            Vs[r * AST + lc + 2] = f2tf32(pv[l].z);
            Vs[r * AST + lc + 3] = f2tf32(pv[l].w);
        }
        __syncthreads();

        // prefetch next tile K/V into registers (overlaps with S mma)
        if (sT + 1 < nS) {
            const size_t base = (size_t)((sT + 1) * 64) * Dq;
#pragma unroll
            for (int l = 0; l < 4; l++) {
                int r = lr + l * 16;
                pk[l] = *(const float4*)(kb + base + (size_t)r * Dq + lc);
                pv[l] = *(const float4*)(vb + base + (size_t)r * Dq + lc);
            }
        }

        // S = Q·K^T, causal mask on diagonal band
        float sacc[8][4];
#pragma unroll
        for (int nt = 0; nt < 8; nt++)
            { sacc[nt][0]=0.f; sacc[nt][1]=0.f; sacc[nt][2]=0.f; sacc[nt][3]=0.f; }
#pragma unroll
        for (int ks = 0; ks < 8; ks++) {
            uint32_t bf[8][2];
#pragma unroll
            for (int nt = 0; nt < 8; nt++) {
                int srow = nt * 8 + (lane >> 2);
                int scol = ks * 8 + (lane & 3);
                bf[nt][0] = __float_as_uint(Ks[srow * AST + scol]);
                bf[nt][1] = __float_as_uint(Ks[srow * AST + scol + 4]);
            }
#pragma unroll
            for (int nt = 0; nt < 8; nt++)
                mma_tf32(sacc[nt], af[ks][0], af[ks][1], af[ks][2], af[ks][3],
                         bf[nt][0], bf[nt][1]);
        }

        const bool mask = (sT >= 2 * tB);
        // E = exp(S/8) (no max: scores bounded, diagonal => l >= 1)
        {
            const int pr = wm + (lane >> 2);
            const int pc = (lane & 3) << 1;
#pragma unroll
            for (int nt = 0; nt < 8; nt++) {
                float s0v = sacc[nt][0] * 0.125f;
                float s1v = sacc[nt][1] * 0.125f;
                float s2v = sacc[nt][2] * 0.125f;
                float s3v = sacc[nt][3] * 0.125f;
                if (mask) {
                    int s0 = sT * 64 + nt * 8 + ((lane & 3) << 1);
                    if (s0     > trow0) s0v = -INFINITY;
                    if (s0 + 1 > trow0) s1v = -INFINITY;
                    if (s0     > trow1) s2v = -INFINITY;
                    if (s0 + 1 > trow1) s3v = -INFINITY;
                }
                float e0 = __expf(s0v), e1 = __expf(s1v);
                float e2 = __expf(s2v), e3 = __expf(s3v);
                l0 += e0 + e1;
                l1 += e2 + e3;
                Ps[(pr    ) * AST + nt * 8 + pc    ] = e0;
                Ps[(pr    ) * AST + nt * 8 + pc + 1] = e1;
                Ps[(pr + 8) * AST + nt * 8 + pc    ] = e2;
                Ps[(pr + 8) * AST + nt * 8 + pc + 1] = e3;
            }
        }
        __syncthreads();

        // write unnormalized E tile to wei (coalesced float4)
#pragma unroll
        for (int l = 0; l < 8; l++) {
            int f = tid + l * 256;
            int r = f >> 4, c4 = (f & 15) << 2;
            *(float4*)(wb + (size_t)r * Tq + sT * 64 + c4) = *(const float4*)(Ps + r * AST + c4);
        }

        // ctx += E·V (P rounded rna to tf32; V already rounded in smem)
#pragma unroll
        for (int ks = 0; ks < 8; ks++) {
            const int arow = wm + (lane >> 2);
            const int acol = ks * 8 + (lane & 3);
            uint32_t ap[4];
            ap[0] = __float_as_uint(f2tf32(Ps[(arow    ) * AST + acol    ]));
            ap[1] = __float_as_uint(f2tf32(Ps[(arow + 8) * AST + acol    ]));
            ap[2] = __float_as_uint(f2tf32(Ps[(arow    ) * AST + acol + 4]));
            ap[3] = __float_as_uint(f2tf32(Ps[(arow + 8) * AST + acol + 4]));
            uint32_t bv[8][2];
#pragma unroll
            for (int nt = 0; nt < 8; nt++) {
                int vrow = ks * 8 + (lane & 3);
                int vcol = nt * 8 + (lane >> 2);
                bv[nt][0] = __float_as_uint(Vs[(vrow    ) * AST + vcol]);
                bv[nt][1] = __float_as_uint(Vs[(vrow + 4) * AST + vcol]);
            }
#pragma unroll
            for (int nt = 0; nt < 8; nt++)
                mma_tf32(ctx[nt], ap[0], ap[1], ap[2], ap[3], bv[nt][0], bv[nt][1]);
        }
        __syncthreads();
    }

    // reduce row sums across quad lanes
    l0 += __shfl_xor_sync(0xffffffffu, l0, 1);
    l0 += __shfl_xor_sync(0xffffffffu, l0, 2);
    l1 += __shfl_xor_sync(0xffffffffu, l1, 1);
    l1 += __shfl_xor_sync(0xffffffffu, l1, 2);
    const float inv0 = 1.0f / l0;
    const float inv1 = 1.0f / l1;

    if ((lane & 3) == 0) {
        g_invl[(size_t)bh * Tq + trow0] = inv0;
        g_invl[(size_t)bh * Tq + trow1] = inv1;
    }

    // zero-fill upper triangle region (cols >= nS*64)
    {
        const int nz4 = (16 - nS) * 16;
        if (nz4 > 0) {
            const float4 z = {0.f, 0.f, 0.f, 0.f};
            for (int f = tid; f < 128 * nz4; f += 256) {
                int r  = f / nz4;
                int c4 = (f - r * nz4) << 2;
                *(float4*)(wb + (size_t)r * Tq + nS * 64 + c4) = z;
            }
        }
    }

    // write normalized ctx directly in split (hi|lo) form to g_ctx2 [M, 2C]
    {
        const int b = bh >> 4, h = bh & 15;
        const int ec = (lane & 3) << 1;
        float* r0 = g_ctx2 + (size_t)(b * Tq + trow0) * (2 * Cq);
        float* r1 = g_ctx2 + (size_t)(b * Tq + trow1) * (2 * Cq);
#pragma unroll
        for (int nt = 0; nt < 8; nt++) {
            int c = h * 64 + nt * 8 + ec;
            float v00 = ctx[nt][0] * inv0, v01 = ctx[nt][1] * inv0;
            float v10 = ctx[nt][2] * inv1, v11 = ctx[nt][3] * inv1;
            float h00 = f2tf32(v00), h01 = f2tf32(v01);
            float h10 = f2tf32(v10), h11 = f2tf32(v11);
            *(float2*)(r0 + c)      = make_float2(h00, h01);
            *(float2*)(r0 + Cq + c) = make_float2(f2tf32(v00 - h00), f2tf32(v01 - h01));
            *(float2*)(r1 + c)      = make_float2(h10, h11);
            *(float2*)(r1 + Cq + c) = make_float2(f2tf32(v10 - h10), f2tf32(v11 - h11));
        }
    }
}

// ---------------------------------------------------------------------------
// Rescale wei rows by 1/l (causal region only).
// ---------------------------------------------------------------------------
__global__ __launch_bounds__(256) void rescale_wei(float* __restrict__ wei) {
    const int bh = blockIdx.y;
    const int t  = blockIdx.x * 2 + (threadIdx.x >> 7);
    const int ln = threadIdx.x & 127;
    const float inv = g_invl[(size_t)bh * Tq + t];
    float4* row = (float4*)(wei + (size_t)bh * Tq * Tq + (size_t)t * Tq);
    const int n4 = ((t >> 7) + 1) * 32;
#pragma unroll 2
    for (int w = ln; w < n4; w += 128) {
        float4 v = row[w];
        v.x *= inv; v.y *= inv; v.z *= inv; v.w *= inv;
        row[w] = v;
    }
}

// ---------------------------------------------------------------------------
// Launch
// ---------------------------------------------------------------------------
extern "C" void kernel_launch(void* const* d_in, const int* in_sizes, int n_in,
                              void* d_out, int out_size) {
    const float* x     = (const float*)d_in[0];
    const float* Wq    = (const float*)d_in[1];
    const float* Wk    = (const float*)d_in[2];
    const float* Wv    = (const float*)d_in[3];
    const float* Wproj = (const float*)d_in[4];
    const float* bproj = (const float*)d_in[5];

    float* out = (float*)d_out;                       // [B,T,C]
    float* wei = out + (size_t)Bq * Tq * Cq;          // [B,H,T,T]

    float *pq, *pk, *pv, *pxt, *pwqkv, *pctx2, *pwp2;
    cudaGetSymbolAddress((void**)&pq,    g_q);
    cudaGetSymbolAddress((void**)&pk,    g_k);
    cudaGetSymbolAddress((void**)&pv,    g_v);
    cudaGetSymbolAddress((void**)&pxt,   g_xt);
    cudaGetSymbolAddress((void**)&pwqkv, g_wqkv);
    cudaGetSymbolAddress((void**)&pctx2, g_ctx2);
    cudaGetSymbolAddress((void**)&pwp2,  g_wp2);

    const int attn_smem = ATTN_SMEM_FLOATS * 4;
    cudaFuncSetAttribute(attn_fused, cudaFuncAttributeMaxDynamicSharedMemorySize, attn_smem);
    cudaFuncSetAttribute(gemm_mma2, cudaFuncAttributeMaxDynamicSharedMemorySize, GEMM_SMEM_BYTES);

    // 1) tf32 rounding / repacking of GEMM inputs
    conv_x4_kernel<<<(Mq * Cq / 4) / 256, 256>>>((const float4*)x, (float4*)pxt);
    dim3 gw((Cq * Cq) / 256, 3);
    conv_wqkv3_kernel<<<gw, 256>>>(Wq, Wk, Wv, pwqkv);
    conv_wp2_kernel<<<(Cq * Cq) / 256, 256>>>(Wproj, pwp2);

    // 2) Q/K/V projections: one z=3 grid on tensor cores
    dim3 gqkv(Cq / 128, Mq / 128, 3);
    gemm_mma2<<<gqkv, 256, GEMM_SMEM_BYTES>>>(pxt, pwqkv, pq, pk, pv, Cq, Cq, 1, nullptr);

    // 3) fused one-pass attention (wei unnormalized; ctx2 split written direct)
    dim3 gattn(Tq / 128, BHq);
    attn_fused<<<gattn, 256, attn_smem>>>(wei);

    // 4) normalize wei rows
    dim3 grs(Tq / 2, BHq);
    rescale_wei<<<grs, 256>>>(wei);

    // 5) out = ctx @ Wproj^T + b  via 2-term tf32 split (K=2048)
    dim3 gout(Cq / 128, Mq / 128, 1);
    gemm_mma2<<<gout, 256, GEMM_SMEM_BYTES>>>(pctx2, pwp2, out, nullptr, nullptr,
                                              2 * Cq, Cq, 0, bproj);
}

// round 9
// speedup vs baseline: 2.8427x; 1.0480x over previous
#include <cuda_runtime.h>
#include <math.h>
#include <stdint.h>

// Problem constants
#define Bq 8
#define Tq 1024
#define Cq 1024
#define Hq 16
#define Dq 64
#define Mq (Bq * Tq)          // 8192 rows
#define BHq (Bq * Hq)         // 128

// ---------------------------------------------------------------------------
// Scratch (device globals; no dynamic allocation allowed)
// ---------------------------------------------------------------------------
__device__ float g_q[(size_t)BHq * Tq * Dq];      // [B,H,T,D]  32 MB
__device__ float g_k[(size_t)BHq * Tq * Dq];      // 32 MB
__device__ float g_v[(size_t)BHq * Tq * Dq];      // 32 MB
__device__ float g_ctx[(size_t)Mq * Cq];          // [B,T,C] fp32  32 MB
__device__ float g_wqkv[(size_t)3 * Cq * Cq];     // packed [3][N=HD][K=C] tf32
__device__ float g_wp[(size_t)Cq * Cq];           // Wproj tf32 [N,K]  4 MB
__device__ float g_invl[(size_t)BHq * Tq];        // 1/rowsum per (bh,t)

__device__ __forceinline__ float f2tf32(float a) {
    uint32_t r;
    asm("cvt.rna.tf32.f32 %0, %1;" : "=r"(r) : "f"(a));
    return __uint_as_float(r);
}
__device__ __forceinline__ uint32_t smem_u32(const void* p) {
    uint32_t a;
    asm("{ .reg .u64 t; cvta.to.shared.u64 t, %1; cvt.u32.u64 %0, t; }" : "=r"(a) : "l"(p));
    return a;
}

// ---------------------------------------------------------------------------
// Conversion / repack kernels
// ---------------------------------------------------------------------------
// Wq/Wk/Wv [H,C,D] -> packed [3][N=HD][K=C], tf32; blockIdx.y selects matrix
__global__ void conv_wqkv3_kernel(const float* __restrict__ Wq,
                                  const float* __restrict__ Wk,
                                  const float* __restrict__ Wv,
                                  float* __restrict__ P) {
    int i = blockIdx.x * blockDim.x + threadIdx.x;
    int z = blockIdx.y;
    const float* W = (z == 0) ? Wq : (z == 1) ? Wk : Wv;
    int n = i >> 10;
    int c = i & 1023;
    int h = n >> 6, d = n & 63;
    P[(size_t)z * Cq * Cq + (size_t)n * Cq + c] = f2tf32(W[((size_t)h * Cq + c) * Dq + d]);
}

// Wproj [N,K] -> tf32 [N,K] elementwise
__global__ void conv_wp_kernel(const float4* __restrict__ W, float4* __restrict__ P) {
    int i = blockIdx.x * blockDim.x + threadIdx.x;
    float4 v = W[i];
    v.x = f2tf32(v.x); v.y = f2tf32(v.y); v.z = f2tf32(v.z); v.w = f2tf32(v.w);
    P[i] = v;
}

// ---------------------------------------------------------------------------
// mma helper
// ---------------------------------------------------------------------------
__device__ __forceinline__ void mma_tf32(float c[4], uint32_t a0, uint32_t a1,
                                         uint32_t a2, uint32_t a3,
                                         uint32_t b0, uint32_t b1) {
    asm volatile(
        "mma.sync.aligned.m16n8k8.row.col.f32.tf32.tf32.f32 "
        "{%0,%1,%2,%3}, {%4,%5,%6,%7}, {%8,%9}, {%0,%1,%2,%3};"
        : "+f"(c[0]), "+f"(c[1]), "+f"(c[2]), "+f"(c[3])
        : "r"(a0), "r"(a1), "r"(a2), "r"(a3), "r"(b0), "r"(b1));
}

// ---------------------------------------------------------------------------
// Shared GEMM plumbing: CTA tile 128x128, K-chunk 32, 3-stage cp.async,
// 256 threads (8 warps 4x2, warp tile 32x64). A[M,K], B[N,K] row-major.
// ---------------------------------------------------------------------------
#define GST 36
#define STGF (2 * 128 * GST)               // floats per stage (A + B)
#define GEMM_SMEM_BYTES (3 * STGF * 4)     // 110592 B

#define GEMM_PRELUDE(Asrc, Bsrc, Ktot)                                          \
    const int tid  = threadIdx.x;                                               \
    const int wid  = tid >> 5;                                                  \
    const int lane = tid & 31;                                                  \
    const int row0 = blockIdx.y * 128;                                          \
    const int col0 = blockIdx.x * 128;                                          \
    const int wm   = (wid & 3) * 32;                                            \
    const int wn   = (wid >> 2) * 64;                                           \
    const uint32_t smb = smem_u32(smem);                                        \
    int lrow[4], lc4[4];                                                        \
    _Pragma("unroll")                                                           \
    for (int l = 0; l < 4; l++) {                                               \
        int idx = l * 256 + tid;                                                \
        lrow[l] = idx >> 3;                                                     \
        lc4[l]  = (idx & 7) << 2;                                               \
    }                                                                           \
    const int NC = (Ktot) >> 5;

#define ISSUE_STAGE(s, buf, Asrc, Bsrc, Ktot)                                   \
    do {                                                                        \
        const int k0 = (s) << 5;                                                \
        const uint32_t sb = smb + (uint32_t)(buf) * (STGF * 4);                 \
        _Pragma("unroll")                                                       \
        for (int l = 0; l < 4; l++) {                                           \
            uint32_t da = sb + (uint32_t)(lrow[l] * GST + lc4[l]) * 4;          \
            const float* sa = (Asrc) + (size_t)(row0 + lrow[l]) * (Ktot) + k0 + lc4[l]; \
            asm volatile("cp.async.cg.shared.global [%0], [%1], 16;"            \
                         :: "r"(da), "l"(sa));                                  \
            uint32_t db = sb + (uint32_t)(128 * GST + lrow[l] * GST + lc4[l]) * 4; \
            const float* sbp = (Bsrc) + (size_t)(col0 + lrow[l]) * (Ktot) + k0 + lc4[l]; \
            asm volatile("cp.async.cg.shared.global [%0], [%1], 16;"            \
                         :: "r"(db), "l"(sbp));                                 \
        }                                                                       \
        asm volatile("cp.async.commit_group;");                                 \
    } while (0)

#define LOAD_B_FRAGS(Bs_, kb)                                                   \
    uint32_t bf[8][2];                                                          \
    {                                                                           \
        const int brow = wn + (lane >> 2);                                      \
        const int bcol = (kb) + (lane & 3);                                     \
        _Pragma("unroll")                                                       \
        for (int nt = 0; nt < 8; nt++) {                                        \
            bf[nt][0] = __float_as_uint(Bs_[(brow + nt * 8) * GST + bcol    ]); \
            bf[nt][1] = __float_as_uint(Bs_[(brow + nt * 8) * GST + bcol + 4]); \
        }                                                                       \
    }

// ---------------------------------------------------------------------------
// QKV GEMM: A = raw x (tf32-rounded at fragment read), B = pre-rounded W.
// grid (8, 64, 3); scatter epilogue into [B,H,T,D].
// ---------------------------------------------------------------------------
__global__ __launch_bounds__(256) void gemm_qkv(
    const float* __restrict__ A, const float* __restrict__ BwBase,
    float* __restrict__ O0, float* __restrict__ O1, float* __restrict__ O2)
{
    extern __shared__ float smem[];
    const float* Bw = BwBase + (size_t)blockIdx.z * Cq * Cq;
    float* Cout = (blockIdx.z == 0) ? O0 : (blockIdx.z == 1) ? O1 : O2;

    GEMM_PRELUDE(A, Bw, Cq)

    float acc[2][8][4];
#pragma unroll
    for (int mt = 0; mt < 2; mt++)
#pragma unroll
        for (int nt = 0; nt < 8; nt++)
#pragma unroll
            for (int j = 0; j < 4; j++) acc[mt][nt][j] = 0.f;

    ISSUE_STAGE(0, 0, A, Bw, Cq);
    ISSUE_STAGE(1, 1, A, Bw, Cq);
    ISSUE_STAGE(2, 2, A, Bw, Cq);

    int cur = 0;
    for (int i = 0; i < NC; i++) {
        asm volatile("cp.async.wait_group 2;");
        __syncthreads();

        const float* As_ = smem + cur * STGF;
        const float* Bs_ = As_ + 128 * GST;

#pragma unroll
        for (int ks = 0; ks < 4; ks++) {
            const int kb = ks * 8;
            const int arow = wm + (lane >> 2);
            const int acol = kb + (lane & 3);
            uint32_t af[2][4];
#pragma unroll
            for (int mt = 0; mt < 2; mt++) {
                af[mt][0] = __float_as_uint(f2tf32(As_[(arow + mt * 16    ) * GST + acol    ]));
                af[mt][1] = __float_as_uint(f2tf32(As_[(arow + mt * 16 + 8) * GST + acol    ]));
                af[mt][2] = __float_as_uint(f2tf32(As_[(arow + mt * 16    ) * GST + acol + 4]));
                af[mt][3] = __float_as_uint(f2tf32(As_[(arow + mt * 16 + 8) * GST + acol + 4]));
            }
            LOAD_B_FRAGS(Bs_, kb)
#pragma unroll
            for (int mt = 0; mt < 2; mt++)
#pragma unroll
                for (int nt = 0; nt < 8; nt++)
                    mma_tf32(acc[mt][nt], af[mt][0], af[mt][1], af[mt][2], af[mt][3],
                             bf[nt][0], bf[nt][1]);
        }
        __syncthreads();

        if (i + 3 < NC) ISSUE_STAGE(i + 3, cur, A, Bw, Cq);
        else asm volatile("cp.async.commit_group;");
        cur = (cur == 2) ? 0 : cur + 1;
    }

    const int er = lane >> 2;
    const int ec = (lane & 3) << 1;
#pragma unroll
    for (int mt = 0; mt < 2; mt++) {
#pragma unroll
        for (int nt = 0; nt < 8; nt++) {
#pragma unroll
            for (int half = 0; half < 2; half++) {
                int m = row0 + wm + mt * 16 + er + half * 8;
                int b = m >> 10, t = m & 1023;
                int n = col0 + wn + nt * 8 + ec;
                int h = n >> 6, d = n & 63;
                float2 v = make_float2(acc[mt][nt][half * 2], acc[mt][nt][half * 2 + 1]);
                *(float2*)(Cout + ((size_t)(b * Hq + h) << 16) + ((size_t)t << 6) + d) = v;
            }
        }
    }
}

// ---------------------------------------------------------------------------
// Proj GEMM: A = raw fp32 ctx; in-register 2-term tf32 split (hi+lo), B = tf32
// Wproj. out[m,n] = sum ctx[m,k] W[n,k] + bias[n]. grid (8, 64).
// ---------------------------------------------------------------------------
__global__ __launch_bounds__(256) void gemm_proj(
    const float* __restrict__ A, const float* __restrict__ Bw,
    float* __restrict__ Cout, const float* __restrict__ bias)
{
    extern __shared__ float smem[];

    GEMM_PRELUDE(A, Bw, Cq)

    float acc[2][8][4];
#pragma unroll
    for (int mt = 0; mt < 2; mt++)
#pragma unroll
        for (int nt = 0; nt < 8; nt++)
#pragma unroll
            for (int j = 0; j < 4; j++) acc[mt][nt][j] = 0.f;

    ISSUE_STAGE(0, 0, A, Bw, Cq);
    ISSUE_STAGE(1, 1, A, Bw, Cq);
    ISSUE_STAGE(2, 2, A, Bw, Cq);

    int cur = 0;
    for (int i = 0; i < NC; i++) {
        asm volatile("cp.async.wait_group 2;");
        __syncthreads();

        const float* As_ = smem + cur * STGF;
        const float* Bs_ = As_ + 128 * GST;

#pragma unroll
        for (int ks = 0; ks < 4; ks++) {
            const int kb = ks * 8;
            const int arow = wm + (lane >> 2);
            const int acol = kb + (lane & 3);
            uint32_t ah[2][4], al[2][4];
#pragma unroll
            for (int mt = 0; mt < 2; mt++) {
                float r0 = As_[(arow + mt * 16    ) * GST + acol    ];
                float r1 = As_[(arow + mt * 16 + 8) * GST + acol    ];
                float r2 = As_[(arow + mt * 16    ) * GST + acol + 4];
                float r3 = As_[(arow + mt * 16 + 8) * GST + acol + 4];
                float h0 = f2tf32(r0), h1 = f2tf32(r1), h2 = f2tf32(r2), h3 = f2tf32(r3);
                ah[mt][0] = __float_as_uint(h0); al[mt][0] = __float_as_uint(f2tf32(r0 - h0));
                ah[mt][1] = __float_as_uint(h1); al[mt][1] = __float_as_uint(f2tf32(r1 - h1));
                ah[mt][2] = __float_as_uint(h2); al[mt][2] = __float_as_uint(f2tf32(r2 - h2));
                ah[mt][3] = __float_as_uint(h3); al[mt][3] = __float_as_uint(f2tf32(r3 - h3));
            }
            LOAD_B_FRAGS(Bs_, kb)
#pragma unroll
            for (int mt = 0; mt < 2; mt++)
#pragma unroll
                for (int nt = 0; nt < 8; nt++) {
                    mma_tf32(acc[mt][nt], ah[mt][0], ah[mt][1], ah[mt][2], ah[mt][3],
                             bf[nt][0], bf[nt][1]);
                    mma_tf32(acc[mt][nt], al[mt][0], al[mt][1], al[mt][2], al[mt][3],
                             bf[nt][0], bf[nt][1]);
                }
        }
        __syncthreads();

        if (i + 3 < NC) ISSUE_STAGE(i + 3, cur, A, Bw, Cq);
        else asm volatile("cp.async.commit_group;");
        cur = (cur == 2) ? 0 : cur + 1;
    }

    const int er = lane >> 2;
    const int ec = (lane & 3) << 1;
#pragma unroll
    for (int mt = 0; mt < 2; mt++) {
#pragma unroll
        for (int nt = 0; nt < 8; nt++) {
#pragma unroll
            for (int half = 0; half < 2; half++) {
                int m = row0 + wm + mt * 16 + er + half * 8;
                int n = col0 + wn + nt * 8 + ec;
                float2 v = make_float2(acc[mt][nt][half * 2] + bias[n],
                                       acc[mt][nt][half * 2 + 1] + bias[n + 1]);
                *(float2*)(Cout + (size_t)m * Cq + n) = v;
            }
        }
    }
}

// ---------------------------------------------------------------------------
// Fused attention, one pass, no-max softmax (scores bounded; diagonal => l>=1).
// Writes UNNORMALIZED E=exp(S) to wei; ctx=(E·V)/l fp32 to g_ctx; 1/l saved.
// K/V register-prefetched across s-loop.
// ---------------------------------------------------------------------------
#define AST 72
#define ATTN_SMEM_FLOATS (128 * AST + 64 * AST + 64 * AST + 128 * AST)

__global__ __launch_bounds__(256, 1) void attn_fused(float* __restrict__ wei) {
    extern __shared__ float sm[];
    float* Qs = sm;
    float* Ks = Qs + 128 * AST;
    float* Vs = Ks + 64 * AST;
    float* Ps = Vs + 64 * AST;

    const int tid  = threadIdx.x;
    const int wid  = tid >> 5;
    const int lane = tid & 31;
    const int tB   = blockIdx.x;
    const int bh   = blockIdx.y;
    const int wm   = wid * 16;
    const int trow0 = tB * 128 + wm + (lane >> 2);
    const int trow1 = trow0 + 8;

    const float* qb = g_q + (size_t)bh * Tq * Dq + (size_t)tB * 128 * Dq;
    const float* kb = g_k + (size_t)bh * Tq * Dq;
    const float* vb = g_v + (size_t)bh * Tq * Dq;
    float* wb = wei + (size_t)bh * Tq * Tq + (size_t)tB * 128 * Tq;

    const int lr = tid >> 4;
    const int lc = (tid & 15) << 2;

    // load Q tile (tf32-rounded, once)
#pragma unroll
    for (int l = 0; l < 8; l++) {
        int f = tid + l * 256;
        int r = f >> 4, c4 = (f & 15) << 2;
        float4 v = *(const float4*)(qb + (size_t)r * Dq + c4);
        Qs[r * AST + c4 + 0] = f2tf32(v.x);
        Qs[r * AST + c4 + 1] = f2tf32(v.y);
        Qs[r * AST + c4 + 2] = f2tf32(v.z);
        Qs[r * AST + c4 + 3] = f2tf32(v.w);
    }
    __syncthreads();

    // persistent Q fragments
    uint32_t af[8][4];
    {
        const int arow = wm + (lane >> 2);
#pragma unroll
        for (int ks = 0; ks < 8; ks++) {
            const int acol = ks * 8 + (lane & 3);
            af[ks][0] = __float_as_uint(Qs[(arow    ) * AST + acol    ]);
            af[ks][1] = __float_as_uint(Qs[(arow + 8) * AST + acol    ]);
            af[ks][2] = __float_as_uint(Qs[(arow    ) * AST + acol + 4]);
            af[ks][3] = __float_as_uint(Qs[(arow + 8) * AST + acol + 4]);
        }
    }

    const int nS = 2 * tB + 2;
    float l0 = 0.f, l1 = 0.f;
    float ctx[8][4];
#pragma unroll
    for (int nt = 0; nt < 8; nt++)
        { ctx[nt][0]=0.f; ctx[nt][1]=0.f; ctx[nt][2]=0.f; ctx[nt][3]=0.f; }

    float4 pk[4], pv[4];
#pragma unroll
    for (int l = 0; l < 4; l++) {
        int r = lr + l * 16;
        pk[l] = *(const float4*)(kb + (size_t)r * Dq + lc);
        pv[l] = *(const float4*)(vb + (size_t)r * Dq + lc);
    }

    for (int sT = 0; sT < nS; sT++) {
#pragma unroll
        for (int l = 0; l < 4; l++) {
            int r = lr + l * 16;
            Ks[r * AST + lc + 0] = f2tf32(pk[l].x);
            Ks[r * AST + lc + 1] = f2tf32(pk[l].y);
            Ks[r * AST + lc + 2] = f2tf32(pk[l].z);
            Ks[r * AST + lc + 3] = f2tf32(pk[l].w);
            Vs[r * AST + lc + 0] = f2tf32(pv[l].x);
            Vs[r * AST + lc + 1] = f2tf32(pv[l].y);
            Vs[r * AST + lc + 2] = f2tf32(pv[l].z);
            Vs[r * AST + lc + 3] = f2tf32(pv[l].w);
        }
        __syncthreads();

        if (sT + 1 < nS) {
            const size_t base = (size_t)((sT + 1) * 64) * Dq;
#pragma unroll
            for (int l = 0; l < 4; l++) {
                int r = lr + l * 16;
                pk[l] = *(const float4*)(kb + base + (size_t)r * Dq + lc);
                pv[l] = *(const float4*)(vb + base + (size_t)r * Dq + lc);
            }
        }

        float sacc[8][4];
#pragma unroll
        for (int nt = 0; nt < 8; nt++)
            { sacc[nt][0]=0.f; sacc[nt][1]=0.f; sacc[nt][2]=0.f; sacc[nt][3]=0.f; }
#pragma unroll
        for (int ks = 0; ks < 8; ks++) {
            uint32_t bf[8][2];
#pragma unroll
            for (int nt = 0; nt < 8; nt++) {
                int srow = nt * 8 + (lane >> 2);
                int scol = ks * 8 + (lane & 3);
                bf[nt][0] = __float_as_uint(Ks[srow * AST + scol]);
                bf[nt][1] = __float_as_uint(Ks[srow * AST + scol + 4]);
            }
#pragma unroll
            for (int nt = 0; nt < 8; nt++)
                mma_tf32(sacc[nt], af[ks][0], af[ks][1], af[ks][2], af[ks][3],
                         bf[nt][0], bf[nt][1]);
        }

        const bool mask = (sT >= 2 * tB);
        {
            const int pr = wm + (lane >> 2);
            const int pc = (lane & 3) << 1;
#pragma unroll
            for (int nt = 0; nt < 8; nt++) {
                float s0v = sacc[nt][0] * 0.125f;
                float s1v = sacc[nt][1] * 0.125f;
                float s2v = sacc[nt][2] * 0.125f;
                float s3v = sacc[nt][3] * 0.125f;
                if (mask) {
                    int s0 = sT * 64 + nt * 8 + ((lane & 3) << 1);
                    if (s0     > trow0) s0v = -INFINITY;
                    if (s0 + 1 > trow0) s1v = -INFINITY;
                    if (s0     > trow1) s2v = -INFINITY;
                    if (s0 + 1 > trow1) s3v = -INFINITY;
                }
                float e0 = __expf(s0v), e1 = __expf(s1v);
                float e2 = __expf(s2v), e3 = __expf(s3v);
                l0 += e0 + e1;
                l1 += e2 + e3;
                Ps[(pr    ) * AST + nt * 8 + pc    ] = e0;
                Ps[(pr    ) * AST + nt * 8 + pc + 1] = e1;
                Ps[(pr + 8) * AST + nt * 8 + pc    ] = e2;
                Ps[(pr + 8) * AST + nt * 8 + pc + 1] = e3;
            }
        }
        __syncthreads();

        // write unnormalized E tile to wei
#pragma unroll
        for (int l = 0; l < 8; l++) {
            int f = tid + l * 256;
            int r = f >> 4, c4 = (f & 15) << 2;
            *(float4*)(wb + (size_t)r * Tq + sT * 64 + c4) = *(const float4*)(Ps + r * AST + c4);
        }

        // ctx += E·V (P rna-rounded; V pre-rounded in smem)
#pragma unroll
        for (int ks = 0; ks < 8; ks++) {
            const int arow = wm + (lane >> 2);
            const int acol = ks * 8 + (lane & 3);
            uint32_t ap[4];
            ap[0] = __float_as_uint(f2tf32(Ps[(arow    ) * AST + acol    ]));
            ap[1] = __float_as_uint(f2tf32(Ps[(arow + 8) * AST + acol    ]));
            ap[2] = __float_as_uint(f2tf32(Ps[(arow    ) * AST + acol + 4]));
            ap[3] = __float_as_uint(f2tf32(Ps[(arow + 8) * AST + acol + 4]));
            uint32_t bv[8][2];
#pragma unroll
            for (int nt = 0; nt < 8; nt++) {
                int vrow = ks * 8 + (lane & 3);
                int vcol = nt * 8 + (lane >> 2);
                bv[nt][0] = __float_as_uint(Vs[(vrow    ) * AST + vcol]);
                bv[nt][1] = __float_as_uint(Vs[(vrow + 4) * AST + vcol]);
            }
#pragma unroll
            for (int nt = 0; nt < 8; nt++)
                mma_tf32(ctx[nt], ap[0], ap[1], ap[2], ap[3], bv[nt][0], bv[nt][1]);
        }
        __syncthreads();
    }

    l0 += __shfl_xor_sync(0xffffffffu, l0, 1);
    l0 += __shfl_xor_sync(0xffffffffu, l0, 2);
    l1 += __shfl_xor_sync(0xffffffffu, l1, 1);
    l1 += __shfl_xor_sync(0xffffffffu, l1, 2);
    const float inv0 = 1.0f / l0;
    const float inv1 = 1.0f / l1;

    if ((lane & 3) == 0) {
        g_invl[(size_t)bh * Tq + trow0] = inv0;
        g_invl[(size_t)bh * Tq + trow1] = inv1;
    }

    // zero-fill upper triangle region
    {
        const int nz4 = (16 - nS) * 16;
        if (nz4 > 0) {
            const float4 z = {0.f, 0.f, 0.f, 0.f};
            for (int f = tid; f < 128 * nz4; f += 256) {
                int r  = f / nz4;
                int c4 = (f - r * nz4) << 2;
                *(float4*)(wb + (size_t)r * Tq + nS * 64 + c4) = z;
            }
        }
    }

    // write normalized ctx fp32 -> g_ctx [B,T,C]
    {
        const int b = bh >> 4, h = bh & 15;
        const int ec = (lane & 3) << 1;
#pragma unroll
        for (int nt = 0; nt < 8; nt++) {
            float2 v0 = {ctx[nt][0] * inv0, ctx[nt][1] * inv0};
            float2 v1 = {ctx[nt][2] * inv1, ctx[nt][3] * inv1};
            int c = h * 64 + nt * 8 + ec;
            *(float2*)(g_ctx + ((size_t)(b * Tq + trow0) << 10) + c) = v0;
            *(float2*)(g_ctx + ((size_t)(b * Tq + trow1) << 10) + c) = v1;
        }
    }
}

// ---------------------------------------------------------------------------
// Rescale wei rows by 1/l (causal region only).
// ---------------------------------------------------------------------------
__global__ __launch_bounds__(256) void rescale_wei(float* __restrict__ wei) {
    const int bh = blockIdx.y;
    const int t  = blockIdx.x * 2 + (threadIdx.x >> 7);
    const int ln = threadIdx.x & 127;
    const float inv = g_invl[(size_t)bh * Tq + t];
    float4* row = (float4*)(wei + (size_t)bh * Tq * Tq + (size_t)t * Tq);
    const int n4 = ((t >> 7) + 1) * 32;
#pragma unroll 2
    for (int w = ln; w < n4; w += 128) {
        float4 v = row[w];
        v.x *= inv; v.y *= inv; v.z *= inv; v.w *= inv;
        row[w] = v;
    }
}

// ---------------------------------------------------------------------------
// Launch
// ---------------------------------------------------------------------------
extern "C" void kernel_launch(void* const* d_in, const int* in_sizes, int n_in,
                              void* d_out, int out_size) {
    const float* x     = (const float*)d_in[0];
    const float* Wq    = (const float*)d_in[1];
    const float* Wk    = (const float*)d_in[2];
    const float* Wv    = (const float*)d_in[3];
    const float* Wproj = (const float*)d_in[4];
    const float* bproj = (const float*)d_in[5];

    float* out = (float*)d_out;                       // [B,T,C]
    float* wei = out + (size_t)Bq * Tq * Cq;          // [B,H,T,T]

    float *pq, *pk, *pv, *pctx, *pwqkv, *pwp;
    cudaGetSymbolAddress((void**)&pq,    g_q);
    cudaGetSymbolAddress((void**)&pk,    g_k);
    cudaGetSymbolAddress((void**)&pv,    g_v);
    cudaGetSymbolAddress((void**)&pctx,  g_ctx);
    cudaGetSymbolAddress((void**)&pwqkv, g_wqkv);
    cudaGetSymbolAddress((void**)&pwp,   g_wp);

    const int attn_smem = ATTN_SMEM_FLOATS * 4;
    cudaFuncSetAttribute(attn_fused, cudaFuncAttributeMaxDynamicSharedMemorySize, attn_smem);
    cudaFuncSetAttribute(gemm_qkv,  cudaFuncAttributeMaxDynamicSharedMemorySize, GEMM_SMEM_BYTES);
    cudaFuncSetAttribute(gemm_proj, cudaFuncAttributeMaxDynamicSharedMemorySize, GEMM_SMEM_BYTES);

    // 1) weight repack / rounding
    dim3 gw((Cq * Cq) / 256, 3);
    conv_wqkv3_kernel<<<gw, 256>>>(Wq, Wk, Wv, pwqkv);
    conv_wp_kernel<<<(Cq * Cq / 4) / 256, 256>>>((const float4*)Wproj, (float4*)pwp);

    // 2) Q/K/V projections (reads raw x; rounds at fragment read)
    dim3 gqkv(Cq / 128, Mq / 128, 3);
    gemm_qkv<<<gqkv, 256, GEMM_SMEM_BYTES>>>(x, pwqkv, pq, pk, pv);

    // 3) fused one-pass attention
    dim3 gattn(Tq / 128, BHq);
    attn_fused<<<gattn, 256, attn_smem>>>(wei);

    // 4) normalize wei rows
    dim3 grs(Tq / 2, BHq);
    rescale_wei<<<grs, 256>>>(wei);

    // 5) out = ctx @ Wproj^T + b (in-register 2-term split, K=1024)
    dim3 gout(Cq / 128, Mq / 128);
    gemm_proj<<<gout, 256, GEMM_SMEM_BYTES>>>(pctx, pwp, out, bproj);
}